// round 13
// baseline (speedup 1.0000x reference)
#include <cuda_runtime.h>
#include <cuda_fp16.h>
#include <math.h>
#include <stdint.h>

// ---------------------------------------------------------------------------
// B=1, DIM=256, HEADS=8, HD=32, H=W=64 -> N=4096, MLP=1024
// Layout: [C][N] (NCHW flattened), row stride N=4096.
// ---------------------------------------------------------------------------
#define NPIX 4096
#define DIMC 256
#define MLPC 1024

__device__ float g_xd[NPIX];
__device__ float g_r1[DIMC * NPIX];
__device__ float g_rgbln[DIMC * NPIX];
__device__ float g_dptln[DIMC * NPIX];
__device__ __half g_q16[DIMC * NPIX];
__device__ __half g_k16[DIMC * NPIX];
__device__ __half g_v16[DIMC * NPIX];
__device__ float g_fused[DIMC * NPIX];
__device__ float g_oln[DIMC * NPIX];
__device__ __half g_h16[MLPC * NPIX];

// fp16 weight pool (converted once per launch)
#define OFF_DE2 0
#define OFF_Q   65536
#define OFF_K   131072
#define OFF_V   196608
#define OFF_O   262144
#define OFF_M1  327680
#define OFF_M2  589824
__device__ __half g_w16[851968];

__device__ __forceinline__ float fexp2(float x) {
    float y;
    asm("ex2.approx.f32 %0, %1;" : "=f"(y) : "f"(x));
    return y;
}
__device__ __forceinline__ uint32_t packh2(float a, float b) {
    __half2 h = __floats2half2_rn(a, b);
    return *(uint32_t*)&h;
}
__device__ __forceinline__ uint32_t packhh(__half a, __half b) {
    __half2 h = __halves2half2(a, b);
    return *(uint32_t*)&h;
}
__device__ __forceinline__ uint32_t s2u(const void* p) {
    uint32_t a;
    asm("{ .reg .u64 t; cvta.to.shared.u64 t, %1; cvt.u32.u64 %0, t; }" : "=r"(a) : "l"(p));
    return a;
}
__device__ __forceinline__ void mma_f16(float c[4], const uint32_t a[4], const uint32_t b[2]) {
    asm volatile(
        "mma.sync.aligned.m16n8k16.row.col.f32.f16.f16.f32 "
        "{%0,%1,%2,%3}, {%4,%5,%6,%7}, {%8,%9}, {%0,%1,%2,%3};"
        : "+f"(c[0]), "+f"(c[1]), "+f"(c[2]), "+f"(c[3])
        : "r"(a[0]), "r"(a[1]), "r"(a[2]), "r"(a[3]), "r"(b[0]), "r"(b[1]));
}
#define LDSM4(r, addr) \
    asm volatile("ldmatrix.sync.aligned.m8n8.x4.shared.b16 {%0,%1,%2,%3}, [%4];" \
                 : "=r"((r)[0]), "=r"((r)[1]), "=r"((r)[2]), "=r"((r)[3]) : "r"(addr))
#define CP16(d, s) \
    asm volatile("cp.async.cg.shared.global [%0], [%1], 16;" :: "r"(d), "l"(s))
#define CP_COMMIT() asm volatile("cp.async.commit_group;")
#define CP_WAIT0() asm volatile("cp.async.wait_group 0;" ::: "memory")

// ---------------------------------------------------------------------------
// Weight fp32 -> fp16 conversion (once per launch). grid (128, 7).
// ---------------------------------------------------------------------------
__global__ void cvt_weights(const float* __restrict__ de2, const float* __restrict__ q,
                            const float* __restrict__ k, const float* __restrict__ v,
                            const float* __restrict__ o, const float* __restrict__ m1,
                            const float* __restrict__ m2, __half* __restrict__ out) {
    int r = blockIdx.y;
    const float* src;
    __half* dst;
    int n;
    switch (r) {
        case 0: src = de2; dst = out + OFF_DE2; n = 65536; break;
        case 1: src = q;   dst = out + OFF_Q;   n = 65536; break;
        case 2: src = k;   dst = out + OFF_K;   n = 65536; break;
        case 3: src = v;   dst = out + OFF_V;   n = 65536; break;
        case 4: src = o;   dst = out + OFF_O;   n = 65536; break;
        case 5: src = m1;  dst = out + OFF_M1;  n = 262144; break;
        default: src = m2; dst = out + OFF_M2;  n = 262144; break;
    }
    int idx = (blockIdx.x * 256 + threadIdx.x) * 8;
    if (idx >= n) return;
    float4 f0 = *(const float4*)(src + idx);
    float4 f1 = *(const float4*)(src + idx + 4);
    uint4 u;
    u.x = packh2(f0.x, f0.y); u.y = packh2(f0.z, f0.w);
    u.z = packh2(f1.x, f1.y); u.w = packh2(f1.z, f1.w);
    *(uint4*)(dst + idx) = u;
}

// ---------------------------------------------------------------------------
// Bilinear 16x downsample 1024x1024 -> 64x64 (align_corners=False)
// ---------------------------------------------------------------------------
__global__ void downsample_kernel(const float* __restrict__ x, float* __restrict__ xd) {
    int p = blockIdx.x * 256 + threadIdx.x;
    int i = p >> 6, j = p & 63;
    int base = (16 * i + 7) * 1024 + (16 * j + 7);
    xd[p] = 0.25f * (x[base] + x[base + 1] + x[base + 1024] + x[base + 1025]);
}

// conv3x3 (1 in, 256 out) + bias + relu
__global__ void conv3_kernel(const float* __restrict__ xd, const float* __restrict__ w,
                             const float* __restrict__ bias, float* __restrict__ y) {
    __shared__ float s_xd[NPIX];
    int tid = threadIdx.x;
    int o = blockIdx.x;
    for (int e = tid; e < NPIX; e += 256) s_xd[e] = xd[e];
    __syncthreads();
    float wr[9];
#pragma unroll
    for (int t = 0; t < 9; ++t) wr[t] = w[o * 9 + t];
    float bv = bias[o];
    for (int it = 0; it < 16; ++it) {
        int p = tid + it * 256;
        int i = p >> 6, j = p & 63;
        float acc = bv;
#pragma unroll
        for (int di = 0; di < 3; ++di) {
            int ii = i + di - 1;
            if (ii < 0 || ii > 63) continue;
#pragma unroll
            for (int dj = 0; dj < 3; ++dj) {
                int jj = j + dj - 1;
                if (jj < 0 || jj > 63) continue;
                acc = fmaf(wr[di * 3 + dj], s_xd[ii * 64 + jj], acc);
            }
        }
        y[o * NPIX + p] = fmaxf(acc, 0.0f);
    }
}

// ---------------------------------------------------------------------------
// GEMM fp16 m16n8k16, ldmatrix + cp.async (validated R9-R12).
// ---------------------------------------------------------------------------
#define GEMM_SMEM 30720

template <int ACT, int OUT16>
__device__ __forceinline__ void gemm_body(
    const __half* __restrict__ W16, const float* __restrict__ X,
    const float* __restrict__ bias, void* __restrict__ Yv,
    int M, int K, int N, int m0, int n0, float oscale) {
    extern __shared__ uint32_t sm[];
    uint32_t sbase = s2u(sm);
    uint32_t Ab_[2] = {sbase, sbase + 10240};
    uint32_t Bb_[2] = {sbase + 20480, sbase + 25600};
    uint32_t* BsW[2] = {sm + 5120, sm + 6400};

    int tid = threadIdx.x;
    int wid = tid >> 5, lane = tid & 31;
    int wm = wid >> 1, wn = wid & 1;

    int arow = tid >> 2, aslot = tid & 3;
    int bn = tid & 63, bks = tid >> 6;

    uint32_t a_off = (uint32_t)(wm * 32 + (lane & 7) + ((lane >> 3) & 1) * 8) * 80
                   + (uint32_t)(lane >> 4) * 16;
    uint32_t b_off = (uint32_t)(wn * 32 + (lane & 7) + ((lane >> 4) & 1) * 8) * 80
                   + (uint32_t)((lane >> 3) & 1) * 16;

    const int C = K >> 5;
    float br[8];

    CP16(Ab_[0] + arow * 80 + aslot * 16, W16 + (size_t)(m0 + arow) * K + aslot * 8);
    CP16(Ab_[0] + (arow + 64) * 80 + aslot * 16, W16 + (size_t)(m0 + arow + 64) * K + aslot * 8);
    CP_COMMIT();
#pragma unroll
    for (int j = 0; j < 8; ++j)
        br[j] = X[(size_t)(bks * 8 + j) * N + n0 + bn];

    float acc[2][4][4];
#pragma unroll
    for (int t = 0; t < 2; ++t)
#pragma unroll
        for (int u = 0; u < 4; ++u)
#pragma unroll
            for (int e = 0; e < 4; ++e) acc[t][u][e] = 0.0f;

#pragma unroll
    for (int j2 = 0; j2 < 4; ++j2)
        BsW[0][bn * 20 + bks * 4 + j2] = packh2(br[2 * j2], br[2 * j2 + 1]);
    CP_WAIT0();
    __syncthreads();

    for (int c = 0; c < C; ++c) {
        if (c + 1 < C) {
            int k0 = (c + 1) << 5;
            uint32_t ab = Ab_[(c + 1) & 1];
            CP16(ab + arow * 80 + aslot * 16, W16 + (size_t)(m0 + arow) * K + k0 + aslot * 8);
            CP16(ab + (arow + 64) * 80 + aslot * 16,
                 W16 + (size_t)(m0 + arow + 64) * K + k0 + aslot * 8);
            CP_COMMIT();
#pragma unroll
            for (int j = 0; j < 8; ++j)
                br[j] = X[(size_t)(k0 + bks * 8 + j) * N + n0 + bn];
        }

        uint32_t Abuf = Ab_[c & 1], Bbuf = Bb_[c & 1];
#pragma unroll
        for (int ks = 0; ks < 2; ++ks) {
            uint32_t a0[4], a1[4], b01[4], b23[4];
            LDSM4(a0, Abuf + a_off + ks * 32);
            LDSM4(a1, Abuf + a_off + 16 * 80 + ks * 32);
            LDSM4(b01, Bbuf + b_off + ks * 32);
            LDSM4(b23, Bbuf + b_off + 16 * 80 + ks * 32);
            mma_f16(acc[0][0], a0, b01);
            mma_f16(acc[0][1], a0, b01 + 2);
            mma_f16(acc[0][2], a0, b23);
            mma_f16(acc[0][3], a0, b23 + 2);
            mma_f16(acc[1][0], a1, b01);
            mma_f16(acc[1][1], a1, b01 + 2);
            mma_f16(acc[1][2], a1, b23);
            mma_f16(acc[1][3], a1, b23 + 2);
        }

        if (c + 1 < C) {
            CP_WAIT0();
            uint32_t* bw = BsW[(c + 1) & 1];
#pragma unroll
            for (int j2 = 0; j2 < 4; ++j2)
                bw[bn * 20 + bks * 4 + j2] = packh2(br[2 * j2], br[2 * j2 + 1]);
        }
        __syncthreads();
    }

    int g = lane >> 2, tg = lane & 3;
#pragma unroll
    for (int t = 0; t < 2; ++t) {
        int m1 = m0 + wm * 32 + t * 16 + g;
        int m2 = m1 + 8;
        float bv1 = bias[m1], bv2 = bias[m2];
#pragma unroll
        for (int u = 0; u < 4; ++u) {
            int n = n0 + wn * 32 + u * 8 + 2 * tg;
            float v0 = acc[t][u][0] + bv1;
            float v1 = acc[t][u][1] + bv1;
            float v2 = acc[t][u][2] + bv2;
            float v3 = acc[t][u][3] + bv2;
            if (ACT == 2) {
                v0 = 0.5f * v0 * (1.0f + erff(v0 * 0.70710678118654752f));
                v1 = 0.5f * v1 * (1.0f + erff(v1 * 0.70710678118654752f));
                v2 = 0.5f * v2 * (1.0f + erff(v2 * 0.70710678118654752f));
                v3 = 0.5f * v3 * (1.0f + erff(v3 * 0.70710678118654752f));
            }
            if (OUT16) {
                uint32_t* y16 = (uint32_t*)Yv;
                v0 *= oscale; v1 *= oscale; v2 *= oscale; v3 *= oscale;
                y16[(size_t)m1 * (N >> 1) + (n >> 1)] = packh2(v0, v1);
                y16[(size_t)m2 * (N >> 1) + (n >> 1)] = packh2(v2, v3);
            } else {
                float* Y = (float*)Yv;
                *(float2*)(Y + (size_t)m1 * N + n) = make_float2(v0, v1);
                *(float2*)(Y + (size_t)m2 * N + n) = make_float2(v2, v3);
            }
        }
    }
}

template <int ACT, int OUT16>
__global__ void __launch_bounds__(256, 2)
gemm_mma(const __half* __restrict__ W16, const float* __restrict__ X,
         const float* __restrict__ bias, void* __restrict__ Y,
         int M, int K, int N) {
    gemm_body<ACT, OUT16>(W16, X, bias, Y, M, K, N, blockIdx.y * 128, blockIdx.x * 64, 1.0f);
}

__global__ void __launch_bounds__(256, 2)
gemm_qkv(const __half* __restrict__ w16, const float* __restrict__ bq,
         const float* __restrict__ bk, const float* __restrict__ bv,
         const float* __restrict__ xq, const float* __restrict__ xkv,
         __half* __restrict__ q, __half* __restrict__ k, __half* __restrict__ v,
         const float* __restrict__ scale_ptr) {
    int z = blockIdx.z;
    const __half* W = w16 + (z == 0 ? OFF_Q : (z == 1 ? OFF_K : OFF_V));
    const float* B = (z == 0) ? bq : (z == 1) ? bk : bv;
    const float* X = (z == 0) ? xq : xkv;
    __half* Y = (z == 0) ? q : (z == 1) ? k : v;
    float osc = (z == 0) ? (1.4426950408889634f / scale_ptr[0]) : 1.0f;
    gemm_body<0, 1>(W, X, B, (void*)Y, DIMC, DIMC, NPIX,
                    blockIdx.y * 128, blockIdx.x * 64, osc);
}

// ---------------------------------------------------------------------------
// Full-column GEMM (M=256) + fused LayerNorm epilogue.
// 256 threads (8 warps x 32 m-rows), N-tile 16 px, grid 256 -> 256 CTAs
// co-resident (occ 2): fixes R12's grid<SM-count error.
// Smem u32 (43520B): A[2][256][20], B[2][16][20]; epilogue Es[256][17]+sums.
// XF16: X fp16 [k][n].
// ---------------------------------------------------------------------------
#define GLN_SMEM 43520

template <int EPI, int XF16>
__global__ void __launch_bounds__(256, 2)
gemm_ln(const __half* __restrict__ W16, const void* __restrict__ Xv,
        const float* __restrict__ bias, const float* __restrict__ res,
        const float* __restrict__ lng, const float* __restrict__ lnb,
        float* __restrict__ Y, int K,
        const float* __restrict__ s1x, const float* __restrict__ s1g,
        const float* __restrict__ s1b,
        const float* __restrict__ s2x, const float* __restrict__ s2g,
        const float* __restrict__ s2b,
        const float* __restrict__ pos,
        float* __restrict__ y1, float* __restrict__ y2) {
    extern __shared__ uint32_t sm[];
    uint32_t sbase = s2u(sm);
    uint32_t Ab_[2] = {sbase, sbase + 20480};
    uint32_t Bb_[2] = {sbase + 40960, sbase + 42240};
    uint32_t* BsW[2] = {sm + 10240, sm + 10560};
    const float* Xf = (const float*)Xv;
    const __half* Xh = (const __half*)Xv;

    int tid = threadIdx.x;
    int wid = tid >> 5, lane = tid & 31;
    int n0 = blockIdx.x * 16;

    int arow = tid >> 2, aslot = tid & 3;   // A: rows arow + i*64
    int bn = tid & 15, bj = tid >> 4;       // B: pixel, kpair 0..15

    uint32_t a_off = (uint32_t)(wid * 32 + (lane & 7) + ((lane >> 3) & 1) * 8) * 80
                   + (uint32_t)(lane >> 4) * 16;
    uint32_t b_off = (uint32_t)((lane & 7) + ((lane >> 4) & 1) * 8) * 80
                   + (uint32_t)((lane >> 3) & 1) * 16;

    const int C = K >> 5;
    uint32_t bpk;

#pragma unroll
    for (int i = 0; i < 4; ++i)
        CP16(Ab_[0] + (arow + i * 64) * 80 + aslot * 16,
             W16 + (size_t)(arow + i * 64) * K + aslot * 8);
    CP_COMMIT();
    {
        int kk = bj * 2;
        bpk = XF16 ? packhh(Xh[(size_t)kk * NPIX + n0 + bn], Xh[(size_t)(kk + 1) * NPIX + n0 + bn])
                   : packh2(Xf[(size_t)kk * NPIX + n0 + bn], Xf[(size_t)(kk + 1) * NPIX + n0 + bn]);
    }

    float acc[2][2][4];
#pragma unroll
    for (int t = 0; t < 2; ++t)
#pragma unroll
        for (int u = 0; u < 2; ++u)
#pragma unroll
            for (int e = 0; e < 4; ++e) acc[t][u][e] = 0.0f;

    BsW[0][bn * 20 + bj] = bpk;
    CP_WAIT0();
    __syncthreads();

    for (int c = 0; c < C; ++c) {
        if (c + 1 < C) {
            int k0 = (c + 1) << 5;
            uint32_t ab = Ab_[(c + 1) & 1];
#pragma unroll
            for (int i = 0; i < 4; ++i)
                CP16(ab + (arow + i * 64) * 80 + aslot * 16,
                     W16 + (size_t)(arow + i * 64) * K + k0 + aslot * 8);
            CP_COMMIT();
            int kk = k0 + bj * 2;
            bpk = XF16 ? packhh(Xh[(size_t)kk * NPIX + n0 + bn],
                                Xh[(size_t)(kk + 1) * NPIX + n0 + bn])
                       : packh2(Xf[(size_t)kk * NPIX + n0 + bn],
                                Xf[(size_t)(kk + 1) * NPIX + n0 + bn]);
        }

        uint32_t Abuf = Ab_[c & 1], Bbuf = Bb_[c & 1];
#pragma unroll
        for (int ks = 0; ks < 2; ++ks) {
            uint32_t a0[4], a1[4], b01[4];
            LDSM4(a0, Abuf + a_off + ks * 32);
            LDSM4(a1, Abuf + a_off + 16 * 80 + ks * 32);
            LDSM4(b01, Bbuf + b_off + ks * 32);
            mma_f16(acc[0][0], a0, b01);
            mma_f16(acc[0][1], a0, b01 + 2);
            mma_f16(acc[1][0], a1, b01);
            mma_f16(acc[1][1], a1, b01 + 2);
        }

        if (c + 1 < C) {
            CP_WAIT0();
            BsW[(c + 1) & 1][bn * 20 + bj] = bpk;
        }
        __syncthreads();
    }

    // epilogue: Es[256][17] fp32 + partials (alias smem)
    float* Es = (float*)sm;
    float* sp = Es + 4352;   // [16][16]
    float* sq = sp + 256;
    int g = lane >> 2, tg = lane & 3;

#pragma unroll
    for (int t = 0; t < 2; ++t) {
        int r0 = wid * 32 + t * 16 + g, r1 = r0 + 8;
        float bv0 = bias[r0], bv1 = bias[r1];
#pragma unroll
        for (int u = 0; u < 2; ++u) {
            int n = u * 8 + 2 * tg;
            float v0 = acc[t][u][0] + bv0, v1 = acc[t][u][1] + bv0;
            float v2 = acc[t][u][2] + bv1, v3 = acc[t][u][3] + bv1;
            if (EPI == 1) {
                size_t gi0 = (size_t)r0 * NPIX + n0 + n;
                size_t gi1 = (size_t)r1 * NPIX + n0 + n;
                float2 q0 = *(const float2*)(res + gi0);
                float2 q1 = *(const float2*)(res + gi1);
                v0 += q0.x; v1 += q0.y; v2 += q1.x; v3 += q1.y;
            }
            Es[r0 * 17 + n] = v0;
            Es[r0 * 17 + n + 1] = v1;
            Es[r1 * 17 + n] = v2;
            Es[r1 * 17 + n + 1] = v3;
        }
    }
    __syncthreads();

    int px = tid & 15, cg = tid >> 4;  // 16 px x 16 groups of 16 channels
    if (EPI == 1) {
        float e[16], s = 0.0f, q = 0.0f;
#pragma unroll
        for (int i = 0; i < 16; ++i) {
            e[i] = Es[(cg * 16 + i) * 17 + px];
            s += e[i];
            q = fmaf(e[i], e[i], q);
        }
        sp[cg * 16 + px] = s;
        sq[cg * 16 + px] = q;
        __syncthreads();
        float ts = 0.0f, tq = 0.0f;
#pragma unroll
        for (int j = 0; j < 16; ++j) {
            ts += sp[j * 16 + px];
            tq += sq[j * 16 + px];
        }
        float mean = ts * (1.0f / DIMC);
        float rstd = rsqrtf(tq * (1.0f / DIMC) - mean * mean + 1e-5f);
#pragma unroll
        for (int i = 0; i < 16; ++i) {
            int cc = cg * 16 + i;
            Y[(size_t)cc * NPIX + n0 + px] = (e[i] - mean) * rstd * lng[cc] + lnb[cc];
        }
    } else {
        float v[16], s = 0.0f, q = 0.0f;
#pragma unroll
        for (int i = 0; i < 16; ++i) {
            v[i] = s1x[(size_t)(cg * 16 + i) * NPIX + n0 + px];
            s += v[i];
            q = fmaf(v[i], v[i], q);
        }
        sp[cg * 16 + px] = s;
        sq[cg * 16 + px] = q;
        __syncthreads();
        float ts = 0.0f, tq = 0.0f;
#pragma unroll
        for (int j = 0; j < 16; ++j) {
            ts += sp[j * 16 + px];
            tq += sq[j * 16 + px];
        }
        float mean = ts * (1.0f / DIMC);
        float rstd = rsqrtf(tq * (1.0f / DIMC) - mean * mean + 1e-5f);
#pragma unroll
        for (int i = 0; i < 16; ++i) {
            int cc = cg * 16 + i;
            y1[(size_t)cc * NPIX + n0 + px] =
                (v[i] - mean) * rstd * s1g[cc] + s1b[cc] + pos[cc] + Es[cc * 17 + px];
        }
        __syncthreads();
        s = 0.0f; q = 0.0f;
#pragma unroll
        for (int i = 0; i < 16; ++i) {
            v[i] = s2x[(size_t)(cg * 16 + i) * NPIX + n0 + px];
            s += v[i];
            q = fmaf(v[i], v[i], q);
        }
        sp[cg * 16 + px] = s;
        sq[cg * 16 + px] = q;
        __syncthreads();
        ts = 0.0f; tq = 0.0f;
#pragma unroll
        for (int j = 0; j < 16; ++j) {
            ts += sp[j * 16 + px];
            tq += sq[j * 16 + px];
        }
        mean = ts * (1.0f / DIMC);
        rstd = rsqrtf(tq * (1.0f / DIMC) - mean * mean + 1e-5f);
#pragma unroll
        for (int i = 0; i < 16; ++i) {
            int cc = cg * 16 + i;
            y2[(size_t)cc * NPIX + n0 + px] =
                (v[i] - mean) * rstd * s2g[cc] + s2b[cc] + pos[cc] + Es[cc * 17 + px];
        }
    }
}

// ---------------------------------------------------------------------------
// Flash attention, fp16 HMMA + MUFU exp2 + ldmatrix (validated R10/R11;
// near its HMMA roofline, unchanged).
// ---------------------------------------------------------------------------
#define FL_SMEM 37888

__global__ void __launch_bounds__(256, 2)
flash_mma(const __half* __restrict__ Q16, const __half* __restrict__ K16,
          const __half* __restrict__ V16, float* __restrict__ O) {
    extern __shared__ uint32_t fsm[];
    uint32_t* Ks = fsm;               // [2][64][20]
    uint32_t* Vs = fsm + 2560;        // [2][32][36]
    uint32_t* Ps = fsm + 4864;        // [128][36]

    int tid = threadIdx.x;
    int wid = tid >> 5, lane = tid & 31;
    int g = lane >> 2, tg = lane & 3;
    int h = blockIdx.y;
    int n0 = blockIdx.x * 128;
    int r0 = wid * 16 + g, r1 = r0 + 8;

    const __half* Qh = Q16 + (size_t)h * 32 * NPIX;
    const __half* Kh = K16 + (size_t)h * 32 * NPIX;
    const uint32_t* Vhu = (const uint32_t*)(V16 + (size_t)h * 32 * NPIX);

    uint32_t ks_b = s2u(fsm);
    uint32_t vs_b = ks_b + 2560 * 4;
    uint32_t ps_b = ks_b + 4864 * 4;
    uint32_t kfrag = (uint32_t)((lane & 7) + ((lane >> 4) & 1) * 8) * 80
                   + (uint32_t)((lane >> 3) & 1) * 16;
    uint32_t vfrag = (uint32_t)((lane & 7) + ((lane >> 4) & 1) * 8) * 144
                   + (uint32_t)((lane >> 3) & 1) * 16;
    uint32_t pfrag = (uint32_t)(wid * 16 + (lane & 7) + ((lane >> 3) & 1) * 8) * 144
                   + (uint32_t)(lane >> 4) * 16;

    int kkey = tid & 63, kds = tid >> 6;
    int vd = tid >> 4, vslot = tid & 15;

    __half kr[2][4];
    uint2 vr[2];
#pragma unroll
    for (int i = 0; i < 2; ++i) {
        int ds = kds + i * 4;
#pragma unroll
        for (int j = 0; j < 4; ++j)
            kr[i][j] = Kh[(size_t)(ds * 4 + j) * NPIX + kkey];
        vr[i] = *(const uint2*)(Vhu + (size_t)(vd + i * 16) * 2048 + vslot * 2);
    }

    __half* Qsh = (__half*)Ps;
#pragma unroll
    for (int it = 0; it < 4; ++it) {
        int t = tid + it * 256;
        int q4 = t & 31, d = t >> 5;
        uint2 qv = *(const uint2*)(Qh + (size_t)d * NPIX + n0 + q4 * 4);
        const __half* qp = (const __half*)&qv;
        Qsh[(q4 * 4 + 0) * 40 + d] = qp[0];
        Qsh[(q4 * 4 + 1) * 40 + d] = qp[1];
        Qsh[(q4 * 4 + 2) * 40 + d] = qp[2];
        Qsh[(q4 * 4 + 3) * 40 + d] = qp[3];
    }
    __syncthreads();
    uint32_t qa[2][4];
#pragma unroll
    for (int ks = 0; ks < 2; ++ks) {
        int kc = ks * 8 + tg;
        qa[ks][0] = Ps[r0 * 20 + kc];
        qa[ks][1] = Ps[r1 * 20 + kc];
        qa[ks][2] = Ps[r0 * 20 + kc + 4];
        qa[ks][3] = Ps[r1 * 20 + kc + 4];
    }
#pragma unroll
    for (int i = 0; i < 2; ++i) {
        int ds = kds + i * 4;
        *(uint2*)(Ks + kkey * 20 + ds * 2) =
            make_uint2(packhh(kr[i][0], kr[i][1]), packhh(kr[i][2], kr[i][3]));
        *(uint2*)(Vs + (vd + i * 16) * 36 + vslot * 2) = vr[i];
    }
    __syncthreads();

    float m0s = -1e30f, m1s = -1e30f, l0 = 0.0f, l1 = 0.0f;
    float oa[4][4];
#pragma unroll
    for (int u = 0; u < 4; ++u)
#pragma unroll
        for (int e = 0; e < 4; ++e) oa[u][e] = 0.0f;

    for (int kt = 0; kt < 64; ++kt) {
        if (kt + 1 < 64) {
            int mg = (kt + 1) * 64;
#pragma unroll
            for (int i = 0; i < 2; ++i) {
                int ds = kds + i * 4;
#pragma unroll
                for (int j = 0; j < 4; ++j)
                    kr[i][j] = Kh[(size_t)(ds * 4 + j) * NPIX + mg + kkey];
                vr[i] = *(const uint2*)(Vhu + (size_t)(vd + i * 16) * 2048 + (mg >> 1) + vslot * 2);
            }
        }

        uint32_t KsA = ks_b + (kt & 1) * 5120;
        uint32_t VsA = vs_b + (kt & 1) * 4608;

        float sc[8][4];
#pragma unroll
        for (int ns = 0; ns < 8; ++ns)
#pragma unroll
            for (int e = 0; e < 4; ++e) sc[ns][e] = 0.0f;
#pragma unroll
        for (int ks = 0; ks < 2; ++ks) {
#pragma unroll
            for (int nb = 0; nb < 4; ++nb) {
                uint32_t bb[4];
                LDSM4(bb, KsA + nb * 1280 + kfrag + ks * 32);
                mma_f16(sc[2 * nb], qa[ks], bb);
                mma_f16(sc[2 * nb + 1], qa[ks], bb + 2);
            }
        }

        float mx0 = -1e30f, mx1 = -1e30f;
#pragma unroll
        for (int ns = 0; ns < 8; ++ns) {
            mx0 = fmaxf(mx0, fmaxf(sc[ns][0], sc[ns][1]));
            mx1 = fmaxf(mx1, fmaxf(sc[ns][2], sc[ns][3]));
        }
        mx0 = fmaxf(mx0, __shfl_xor_sync(0xffffffffu, mx0, 1));
        mx0 = fmaxf(mx0, __shfl_xor_sync(0xffffffffu, mx0, 2));
        mx1 = fmaxf(mx1, __shfl_xor_sync(0xffffffffu, mx1, 1));
        mx1 = fmaxf(mx1, __shfl_xor_sync(0xffffffffu, mx1, 2));
        float mn0 = fmaxf(m0s, mx0), mn1 = fmaxf(m1s, mx1);
        float c0f = fexp2(m0s - mn0), c1f = fexp2(m1s - mn1);
        float rs0 = 0.0f, rs1 = 0.0f;
#pragma unroll
        for (int ns = 0; ns < 8; ++ns) {
            float p0 = fexp2(sc[ns][0] - mn0);
            float p1 = fexp2(sc[ns][1] - mn0);
            float p2 = fexp2(sc[ns][2] - mn1);
            float p3 = fexp2(sc[ns][3] - mn1);
            rs0 += p0 + p1;
            rs1 += p2 + p3;
            Ps[r0 * 36 + ns * 4 + tg] = packh2(p0, p1);
            Ps[r1 * 36 + ns * 4 + tg] = packh2(p2, p3);
        }
        rs0 += __shfl_xor_sync(0xffffffffu, rs0, 1);
        rs0 += __shfl_xor_sync(0xffffffffu, rs0, 2);
        rs1 += __shfl_xor_sync(0xffffffffu, rs1, 1);
        rs1 += __shfl_xor_sync(0xffffffffu, rs1, 2);
        l0 = l0 * c0f + rs0;
        l1 = l1 * c1f + rs1;
        m0s = mn0; m1s = mn1;
#pragma unroll
        for (int u = 0; u < 4; ++u) {
            oa[u][0] *= c0f; oa[u][1] *= c0f;
            oa[u][2] *= c1f; oa[u][3] *= c1f;
        }
        __syncwarp();

#pragma unroll
        for (int ks = 0; ks < 4; ++ks) {
            uint32_t pa[4], v0[4], v1[4];
            LDSM4(pa, ps_b + pfrag + ks * 32);
            LDSM4(v0, VsA + vfrag + ks * 32);
            LDSM4(v1, VsA + vfrag + 2304 + ks * 32);
            mma_f16(oa[0], pa, v0);
            mma_f16(oa[1], pa, v0 + 2);
            mma_f16(oa[2], pa, v1);
            mma_f16(oa[3], pa, v1 + 2);
        }
        __syncwarp();

        if (kt + 1 < 64) {
            uint32_t* Ksn = Ks + ((kt + 1) & 1) * 1280;
            uint32_t* Vsn = Vs + ((kt + 1) & 1) * 1152;
#pragma unroll
            for (int i = 0; i < 2; ++i) {
                int ds = kds + i * 4;
                *(uint2*)(Ksn + kkey * 20 + ds * 2) =
                    make_uint2(packhh(kr[i][0], kr[i][1]), packhh(kr[i][2], kr[i][3]));
                *(uint2*)(Vsn + (vd + i * 16) * 36 + vslot * 2) = vr[i];
            }
            __syncthreads();
        }
    }

    float il0 = 1.0f / l0, il1 = 1.0f / l1;
#pragma unroll
    for (int ns = 0; ns < 4; ++ns) {
        int d0 = ns * 8 + 2 * tg;
        O[(size_t)(h * 32 + d0) * NPIX + n0 + r0] = oa[ns][0] * il0;
        O[(size_t)(h * 32 + d0 + 1) * NPIX + n0 + r0] = oa[ns][1] * il0;
        O[(size_t)(h * 32 + d0) * NPIX + n0 + r1] = oa[ns][2] * il1;
        O[(size_t)(h * 32 + d0 + 1) * NPIX + n0 + r1] = oa[ns][3] * il1;
    }
}

// ---------------------------------------------------------------------------
extern "C" void kernel_launch(void* const* d_in, const int* in_sizes, int n_in,
                              void* d_out, int out_size) {
    const float* rgb   = (const float*)d_in[0];
    const float* dpt   = (const float*)d_in[1];
    const float* xdpt  = (const float*)d_in[2];
    const float* wq    = (const float*)d_in[3];
    const float* bq    = (const float*)d_in[4];
    const float* wk    = (const float*)d_in[5];
    const float* bk    = (const float*)d_in[6];
    const float* wv    = (const float*)d_in[7];
    const float* bv    = (const float*)d_in[8];
    const float* wo    = (const float*)d_in[9];
    const float* bo    = (const float*)d_in[10];
    const float* ga_rgb = (const float*)d_in[11];
    const float* be_rgb = (const float*)d_in[12];
    const float* ga_dpt = (const float*)d_in[13];
    const float* be_dpt = (const float*)d_in[14];
    const float* ga1   = (const float*)d_in[15];
    const float* be1   = (const float*)d_in[16];
    const float* ga2   = (const float*)d_in[17];
    const float* be2   = (const float*)d_in[18];
    const float* w_mlp1 = (const float*)d_in[19];
    const float* b_mlp1 = (const float*)d_in[20];
    const float* w_mlp2 = (const float*)d_in[21];
    const float* b_mlp2 = (const float*)d_in[22];
    const float* w_de1 = (const float*)d_in[23];
    const float* b_de1 = (const float*)d_in[24];
    const float* w_de2 = (const float*)d_in[25];
    const float* b_de2 = (const float*)d_in[26];
    const float* pos_emb = (const float*)d_in[27];
    const float* scale = (const float*)d_in[28];
    float* out = (float*)d_out;

    float *p_xd, *p_r1, *p_rgbln, *p_dptln, *p_fused, *p_oln;
    __half *p_q16, *p_k16, *p_v16, *p_w16, *p_h16;
    cudaGetSymbolAddress((void**)&p_xd, g_xd);
    cudaGetSymbolAddress((void**)&p_r1, g_r1);
    cudaGetSymbolAddress((void**)&p_rgbln, g_rgbln);
    cudaGetSymbolAddress((void**)&p_dptln, g_dptln);
    cudaGetSymbolAddress((void**)&p_q16, g_q16);
    cudaGetSymbolAddress((void**)&p_k16, g_k16);
    cudaGetSymbolAddress((void**)&p_v16, g_v16);
    cudaGetSymbolAddress((void**)&p_fused, g_fused);
    cudaGetSymbolAddress((void**)&p_oln, g_oln);
    cudaGetSymbolAddress((void**)&p_h16, g_h16);
    cudaGetSymbolAddress((void**)&p_w16, g_w16);

    static bool attr_done = false;
    if (!attr_done) {
        cudaFuncSetAttribute(gemm_mma<2, 1>, cudaFuncAttributeMaxDynamicSharedMemorySize, GEMM_SMEM);
        cudaFuncSetAttribute(gemm_qkv, cudaFuncAttributeMaxDynamicSharedMemorySize, GEMM_SMEM);
        cudaFuncSetAttribute(gemm_ln<0, 0>, cudaFuncAttributeMaxDynamicSharedMemorySize, GLN_SMEM);
        cudaFuncSetAttribute(gemm_ln<1, 0>, cudaFuncAttributeMaxDynamicSharedMemorySize, GLN_SMEM);
        cudaFuncSetAttribute(gemm_ln<1, 1>, cudaFuncAttributeMaxDynamicSharedMemorySize, GLN_SMEM);
        cudaFuncSetAttribute(flash_mma, cudaFuncAttributeMaxDynamicSharedMemorySize, FL_SMEM);
        attr_done = true;
    }

    // weights -> fp16 pool
    cvt_weights<<<dim3(128, 7), 256>>>(w_de2, wq, wk, wv, wo, w_mlp1, w_mlp2, p_w16);

    // depth positional-embedding path
    downsample_kernel<<<16, 256>>>(xdpt, p_xd);
    conv3_kernel<<<256, 256>>>(p_xd, w_de1, b_de1, p_r1);

    // pe GEMM fused with LN(rgb)+pos+pe and LN(dpt)+pos+pe
    gemm_ln<0, 0><<<256, 256, GLN_SMEM>>>(p_w16 + OFF_DE2, p_r1, b_de2, nullptr, nullptr, nullptr,
                                          nullptr, DIMC,
                                          rgb, ga_rgb, be_rgb, dpt, ga_dpt, be_dpt,
                                          pos_emb, p_rgbln, p_dptln);

    // QKV projections
    gemm_qkv<<<dim3(64, 2, 3), 256, GEMM_SMEM>>>(p_w16, bq, bk, bv,
                                                 p_rgbln, p_dptln, p_q16, p_k16, p_v16, scale);

    // flash attention
    flash_mma<<<dim3(32, 8), 256, FL_SMEM>>>(p_q16, p_k16, p_v16, p_fused);

    // output proj + residual + LN1 fused -> oln
    gemm_ln<1, 0><<<256, 256, GLN_SMEM>>>(p_w16 + OFF_O, p_fused, bo, rgb, ga1, be1,
                                          p_oln, DIMC,
                                          nullptr, nullptr, nullptr, nullptr, nullptr,
                                          nullptr, nullptr, nullptr, nullptr);

    // MLP up (exact gelu), fp16 output
    gemm_mma<2, 1><<<dim3(64, 8), 256, GEMM_SMEM>>>(p_w16 + OFF_M1, p_oln, b_mlp1, (void*)p_h16,
                                                    MLPC, DIMC, NPIX);

    // MLP down (fp16 X) + residual + final LN fused -> d_out
    gemm_ln<1, 1><<<256, 256, GLN_SMEM>>>(p_w16 + OFF_M2, p_h16, b_mlp2, p_oln, ga2, be2,
                                          out, MLPC,
                                          nullptr, nullptr, nullptr, nullptr, nullptr,
                                          nullptr, nullptr, nullptr, nullptr);
}

// round 14
// speedup vs baseline: 1.0179x; 1.0179x over previous
#include <cuda_runtime.h>
#include <cuda_fp16.h>
#include <math.h>
#include <stdint.h>

// ---------------------------------------------------------------------------
// B=1, DIM=256, HEADS=8, HD=32, H=W=64 -> N=4096, MLP=1024
// Layout: [C][N] (NCHW flattened), row stride N=4096.
// ---------------------------------------------------------------------------
#define NPIX 4096
#define DIMC 256
#define MLPC 1024

__device__ float g_xd[NPIX];
__device__ float g_r1[DIMC * NPIX];
__device__ float g_rgbln[DIMC * NPIX];
__device__ float g_dptln[DIMC * NPIX];
__device__ __half g_q16[DIMC * NPIX];
__device__ __half g_k16[DIMC * NPIX];
__device__ __half g_v16[DIMC * NPIX];
__device__ float g_fused[DIMC * NPIX];
__device__ float g_oln[DIMC * NPIX];
__device__ __half g_h16[MLPC * NPIX];

// fp16 weight pool (converted once per launch)
#define OFF_DE2 0
#define OFF_Q   65536
#define OFF_K   131072
#define OFF_V   196608
#define OFF_O   262144
#define OFF_M1  327680
#define OFF_M2  589824
__device__ __half g_w16[851968];

__device__ __forceinline__ float fexp2(float x) {
    float y;
    asm("ex2.approx.f32 %0, %1;" : "=f"(y) : "f"(x));
    return y;
}
__device__ __forceinline__ uint32_t packh2(float a, float b) {
    __half2 h = __floats2half2_rn(a, b);
    return *(uint32_t*)&h;
}
__device__ __forceinline__ uint32_t packhh(__half a, __half b) {
    __half2 h = __halves2half2(a, b);
    return *(uint32_t*)&h;
}
__device__ __forceinline__ uint32_t s2u(const void* p) {
    uint32_t a;
    asm("{ .reg .u64 t; cvta.to.shared.u64 t, %1; cvt.u32.u64 %0, t; }" : "=r"(a) : "l"(p));
    return a;
}
__device__ __forceinline__ void mma_f16(float c[4], const uint32_t a[4], const uint32_t b[2]) {
    asm volatile(
        "mma.sync.aligned.m16n8k16.row.col.f32.f16.f16.f32 "
        "{%0,%1,%2,%3}, {%4,%5,%6,%7}, {%8,%9}, {%0,%1,%2,%3};"
        : "+f"(c[0]), "+f"(c[1]), "+f"(c[2]), "+f"(c[3])
        : "r"(a[0]), "r"(a[1]), "r"(a[2]), "r"(a[3]), "r"(b[0]), "r"(b[1]));
}
#define LDSM4(r, addr) \
    asm volatile("ldmatrix.sync.aligned.m8n8.x4.shared.b16 {%0,%1,%2,%3}, [%4];" \
                 : "=r"((r)[0]), "=r"((r)[1]), "=r"((r)[2]), "=r"((r)[3]) : "r"(addr))
#define CP16(d, s) \
    asm volatile("cp.async.cg.shared.global [%0], [%1], 16;" :: "r"(d), "l"(s))
#define CP_COMMIT() asm volatile("cp.async.commit_group;")
#define CP_WAIT0() asm volatile("cp.async.wait_group 0;" ::: "memory")

// ---------------------------------------------------------------------------
// Weight fp32 -> fp16 conversion (once per launch). grid (128, 7).
// ---------------------------------------------------------------------------
__global__ void cvt_weights(const float* __restrict__ de2, const float* __restrict__ q,
                            const float* __restrict__ k, const float* __restrict__ v,
                            const float* __restrict__ o, const float* __restrict__ m1,
                            const float* __restrict__ m2, __half* __restrict__ out) {
    int r = blockIdx.y;
    const float* src;
    __half* dst;
    int n;
    switch (r) {
        case 0: src = de2; dst = out + OFF_DE2; n = 65536; break;
        case 1: src = q;   dst = out + OFF_Q;   n = 65536; break;
        case 2: src = k;   dst = out + OFF_K;   n = 65536; break;
        case 3: src = v;   dst = out + OFF_V;   n = 65536; break;
        case 4: src = o;   dst = out + OFF_O;   n = 65536; break;
        case 5: src = m1;  dst = out + OFF_M1;  n = 262144; break;
        default: src = m2; dst = out + OFF_M2;  n = 262144; break;
    }
    int idx = (blockIdx.x * 256 + threadIdx.x) * 8;
    if (idx >= n) return;
    float4 f0 = *(const float4*)(src + idx);
    float4 f1 = *(const float4*)(src + idx + 4);
    uint4 u;
    u.x = packh2(f0.x, f0.y); u.y = packh2(f0.z, f0.w);
    u.z = packh2(f1.x, f1.y); u.w = packh2(f1.z, f1.w);
    *(uint4*)(dst + idx) = u;
}

// ---------------------------------------------------------------------------
// Bilinear 16x downsample 1024x1024 -> 64x64 (align_corners=False)
// ---------------------------------------------------------------------------
__global__ void downsample_kernel(const float* __restrict__ x, float* __restrict__ xd) {
    int p = blockIdx.x * 256 + threadIdx.x;
    int i = p >> 6, j = p & 63;
    int base = (16 * i + 7) * 1024 + (16 * j + 7);
    xd[p] = 0.25f * (x[base] + x[base + 1] + x[base + 1024] + x[base + 1025]);
}

// conv3x3 (1 in, 256 out) + bias + relu
__global__ void conv3_kernel(const float* __restrict__ xd, const float* __restrict__ w,
                             const float* __restrict__ bias, float* __restrict__ y) {
    __shared__ float s_xd[NPIX];
    int tid = threadIdx.x;
    int o = blockIdx.x;
    for (int e = tid; e < NPIX; e += 256) s_xd[e] = xd[e];
    __syncthreads();
    float wr[9];
#pragma unroll
    for (int t = 0; t < 9; ++t) wr[t] = w[o * 9 + t];
    float bv = bias[o];
    for (int it = 0; it < 16; ++it) {
        int p = tid + it * 256;
        int i = p >> 6, j = p & 63;
        float acc = bv;
#pragma unroll
        for (int di = 0; di < 3; ++di) {
            int ii = i + di - 1;
            if (ii < 0 || ii > 63) continue;
#pragma unroll
            for (int dj = 0; dj < 3; ++dj) {
                int jj = j + dj - 1;
                if (jj < 0 || jj > 63) continue;
                acc = fmaf(wr[di * 3 + dj], s_xd[ii * 64 + jj], acc);
            }
        }
        y[o * NPIX + p] = fmaxf(acc, 0.0f);
    }
}

// ---------------------------------------------------------------------------
// GEMM fp16 m16n8k16, ldmatrix + cp.async (validated R9-R13).
// ---------------------------------------------------------------------------
#define GEMM_SMEM 30720

template <int ACT, int OUT16>
__device__ __forceinline__ void gemm_body(
    const __half* __restrict__ W16, const float* __restrict__ X,
    const float* __restrict__ bias, void* __restrict__ Yv,
    int M, int K, int N, int m0, int n0, float oscale) {
    extern __shared__ uint32_t sm[];
    uint32_t sbase = s2u(sm);
    uint32_t Ab_[2] = {sbase, sbase + 10240};
    uint32_t Bb_[2] = {sbase + 20480, sbase + 25600};
    uint32_t* BsW[2] = {sm + 5120, sm + 6400};

    int tid = threadIdx.x;
    int wid = tid >> 5, lane = tid & 31;
    int wm = wid >> 1, wn = wid & 1;

    int arow = tid >> 2, aslot = tid & 3;
    int bn = tid & 63, bks = tid >> 6;

    uint32_t a_off = (uint32_t)(wm * 32 + (lane & 7) + ((lane >> 3) & 1) * 8) * 80
                   + (uint32_t)(lane >> 4) * 16;
    uint32_t b_off = (uint32_t)(wn * 32 + (lane & 7) + ((lane >> 4) & 1) * 8) * 80
                   + (uint32_t)((lane >> 3) & 1) * 16;

    const int C = K >> 5;
    float br[8];

    CP16(Ab_[0] + arow * 80 + aslot * 16, W16 + (size_t)(m0 + arow) * K + aslot * 8);
    CP16(Ab_[0] + (arow + 64) * 80 + aslot * 16, W16 + (size_t)(m0 + arow + 64) * K + aslot * 8);
    CP_COMMIT();
#pragma unroll
    for (int j = 0; j < 8; ++j)
        br[j] = X[(size_t)(bks * 8 + j) * N + n0 + bn];

    float acc[2][4][4];
#pragma unroll
    for (int t = 0; t < 2; ++t)
#pragma unroll
        for (int u = 0; u < 4; ++u)
#pragma unroll
            for (int e = 0; e < 4; ++e) acc[t][u][e] = 0.0f;

#pragma unroll
    for (int j2 = 0; j2 < 4; ++j2)
        BsW[0][bn * 20 + bks * 4 + j2] = packh2(br[2 * j2], br[2 * j2 + 1]);
    CP_WAIT0();
    __syncthreads();

    for (int c = 0; c < C; ++c) {
        if (c + 1 < C) {
            int k0 = (c + 1) << 5;
            uint32_t ab = Ab_[(c + 1) & 1];
            CP16(ab + arow * 80 + aslot * 16, W16 + (size_t)(m0 + arow) * K + k0 + aslot * 8);
            CP16(ab + (arow + 64) * 80 + aslot * 16,
                 W16 + (size_t)(m0 + arow + 64) * K + k0 + aslot * 8);
            CP_COMMIT();
#pragma unroll
            for (int j = 0; j < 8; ++j)
                br[j] = X[(size_t)(k0 + bks * 8 + j) * N + n0 + bn];
        }

        uint32_t Abuf = Ab_[c & 1], Bbuf = Bb_[c & 1];
#pragma unroll
        for (int ks = 0; ks < 2; ++ks) {
            uint32_t a0[4], a1[4], b01[4], b23[4];
            LDSM4(a0, Abuf + a_off + ks * 32);
            LDSM4(a1, Abuf + a_off + 16 * 80 + ks * 32);
            LDSM4(b01, Bbuf + b_off + ks * 32);
            LDSM4(b23, Bbuf + b_off + 16 * 80 + ks * 32);
            mma_f16(acc[0][0], a0, b01);
            mma_f16(acc[0][1], a0, b01 + 2);
            mma_f16(acc[0][2], a0, b23);
            mma_f16(acc[0][3], a0, b23 + 2);
            mma_f16(acc[1][0], a1, b01);
            mma_f16(acc[1][1], a1, b01 + 2);
            mma_f16(acc[1][2], a1, b23);
            mma_f16(acc[1][3], a1, b23 + 2);
        }

        if (c + 1 < C) {
            CP_WAIT0();
            uint32_t* bw = BsW[(c + 1) & 1];
#pragma unroll
            for (int j2 = 0; j2 < 4; ++j2)
                bw[bn * 20 + bks * 4 + j2] = packh2(br[2 * j2], br[2 * j2 + 1]);
        }
        __syncthreads();
    }

    int g = lane >> 2, tg = lane & 3;
#pragma unroll
    for (int t = 0; t < 2; ++t) {
        int m1 = m0 + wm * 32 + t * 16 + g;
        int m2 = m1 + 8;
        float bv1 = bias[m1], bv2 = bias[m2];
#pragma unroll
        for (int u = 0; u < 4; ++u) {
            int n = n0 + wn * 32 + u * 8 + 2 * tg;
            float v0 = acc[t][u][0] + bv1;
            float v1 = acc[t][u][1] + bv1;
            float v2 = acc[t][u][2] + bv2;
            float v3 = acc[t][u][3] + bv2;
            if (ACT == 2) {
                v0 = 0.5f * v0 * (1.0f + erff(v0 * 0.70710678118654752f));
                v1 = 0.5f * v1 * (1.0f + erff(v1 * 0.70710678118654752f));
                v2 = 0.5f * v2 * (1.0f + erff(v2 * 0.70710678118654752f));
                v3 = 0.5f * v3 * (1.0f + erff(v3 * 0.70710678118654752f));
            }
            if (OUT16) {
                uint32_t* y16 = (uint32_t*)Yv;
                v0 *= oscale; v1 *= oscale; v2 *= oscale; v3 *= oscale;
                y16[(size_t)m1 * (N >> 1) + (n >> 1)] = packh2(v0, v1);
                y16[(size_t)m2 * (N >> 1) + (n >> 1)] = packh2(v2, v3);
            } else {
                float* Y = (float*)Yv;
                *(float2*)(Y + (size_t)m1 * N + n) = make_float2(v0, v1);
                *(float2*)(Y + (size_t)m2 * N + n) = make_float2(v2, v3);
            }
        }
    }
}

template <int ACT, int OUT16>
__global__ void __launch_bounds__(256, 2)
gemm_mma(const __half* __restrict__ W16, const float* __restrict__ X,
         const float* __restrict__ bias, void* __restrict__ Y,
         int M, int K, int N) {
    gemm_body<ACT, OUT16>(W16, X, bias, Y, M, K, N, blockIdx.y * 128, blockIdx.x * 64, 1.0f);
}

__global__ void __launch_bounds__(256, 2)
gemm_qkv(const __half* __restrict__ w16, const float* __restrict__ bq,
         const float* __restrict__ bk, const float* __restrict__ bv,
         const float* __restrict__ xq, const float* __restrict__ xkv,
         __half* __restrict__ q, __half* __restrict__ k, __half* __restrict__ v,
         const float* __restrict__ scale_ptr) {
    int z = blockIdx.z;
    const __half* W = w16 + (z == 0 ? OFF_Q : (z == 1 ? OFF_K : OFF_V));
    const float* B = (z == 0) ? bq : (z == 1) ? bk : bv;
    const float* X = (z == 0) ? xq : xkv;
    __half* Y = (z == 0) ? q : (z == 1) ? k : v;
    float osc = (z == 0) ? (1.4426950408889634f / scale_ptr[0]) : 1.0f;
    gemm_body<0, 1>(W, X, B, (void*)Y, DIMC, DIMC, NPIX,
                    blockIdx.y * 128, blockIdx.x * 64, osc);
}

// ---------------------------------------------------------------------------
// Full-column GEMM (M=256) + fused LayerNorm epilogue — EXACT R11 shape
// (512 thr = 16 warps x m16, N-tile 32, grid 128; best measured), with the
// XF16 template (X fp16 [k][n]) added for the mlp2 path.
// Smem u32 (46080B): A[2][256][20], B[2][32][20]; epilogue Es[256][33]+sums.
// ---------------------------------------------------------------------------
#define GLN_SMEM 46080

template <int EPI, int XF16>
__global__ void __launch_bounds__(512, 1)
gemm_ln(const __half* __restrict__ W16, const void* __restrict__ Xv,
        const float* __restrict__ bias, const float* __restrict__ res,
        const float* __restrict__ lng, const float* __restrict__ lnb,
        float* __restrict__ Y, int K,
        const float* __restrict__ s1x, const float* __restrict__ s1g,
        const float* __restrict__ s1b,
        const float* __restrict__ s2x, const float* __restrict__ s2g,
        const float* __restrict__ s2b,
        const float* __restrict__ pos,
        float* __restrict__ y1, float* __restrict__ y2) {
    extern __shared__ uint32_t sm[];
    uint32_t sbase = s2u(sm);
    uint32_t Ab_[2] = {sbase, sbase + 20480};
    uint32_t Bb_[2] = {sbase + 40960, sbase + 43520};
    uint32_t* BsW[2] = {sm + 10240, sm + 10880};
    const float* Xf = (const float*)Xv;
    const __half* Xh = (const __half*)Xv;

    int tid = threadIdx.x;
    int wid = tid >> 5, lane = tid & 31;
    int wm = wid;
    int n0 = blockIdx.x * 32;

    int arow = tid >> 2, aslot = tid & 3;   // +128 rows on 2nd cp.async
    int bn = tid & 31, bj = tid >> 5;       // B: pixel, k-pair 0..15

    uint32_t a_off = (uint32_t)(wm * 16 + (lane & 7) + ((lane >> 3) & 1) * 8) * 80
                   + (uint32_t)(lane >> 4) * 16;
    uint32_t b_off = (uint32_t)((lane & 7) + ((lane >> 4) & 1) * 8) * 80
                   + (uint32_t)((lane >> 3) & 1) * 16;

    const int C = K >> 5;
    uint32_t bpk;

    CP16(Ab_[0] + arow * 80 + aslot * 16, W16 + (size_t)arow * K + aslot * 8);
    CP16(Ab_[0] + (arow + 128) * 80 + aslot * 16, W16 + (size_t)(arow + 128) * K + aslot * 8);
    CP_COMMIT();
    {
        int kk = bj * 2;
        bpk = XF16 ? packhh(Xh[(size_t)kk * NPIX + n0 + bn], Xh[(size_t)(kk + 1) * NPIX + n0 + bn])
                   : packh2(Xf[(size_t)kk * NPIX + n0 + bn], Xf[(size_t)(kk + 1) * NPIX + n0 + bn]);
    }

    float acc[4][4];
#pragma unroll
    for (int u = 0; u < 4; ++u)
#pragma unroll
        for (int e = 0; e < 4; ++e) acc[u][e] = 0.0f;

    BsW[0][bn * 20 + bj] = bpk;
    CP_WAIT0();
    __syncthreads();

    for (int c = 0; c < C; ++c) {
        if (c + 1 < C) {
            int k0 = (c + 1) << 5;
            uint32_t ab = Ab_[(c + 1) & 1];
            CP16(ab + arow * 80 + aslot * 16, W16 + (size_t)arow * K + k0 + aslot * 8);
            CP16(ab + (arow + 128) * 80 + aslot * 16,
                 W16 + (size_t)(arow + 128) * K + k0 + aslot * 8);
            CP_COMMIT();
            int kk = k0 + bj * 2;
            bpk = XF16 ? packhh(Xh[(size_t)kk * NPIX + n0 + bn],
                                Xh[(size_t)(kk + 1) * NPIX + n0 + bn])
                       : packh2(Xf[(size_t)kk * NPIX + n0 + bn],
                                Xf[(size_t)(kk + 1) * NPIX + n0 + bn]);
        }

        uint32_t Abuf = Ab_[c & 1], Bbuf = Bb_[c & 1];
#pragma unroll
        for (int ks = 0; ks < 2; ++ks) {
            uint32_t a[4], b01[4], b23[4];
            LDSM4(a, Abuf + a_off + ks * 32);
            LDSM4(b01, Bbuf + b_off + ks * 32);
            LDSM4(b23, Bbuf + b_off + 16 * 80 + ks * 32);
            mma_f16(acc[0], a, b01);
            mma_f16(acc[1], a, b01 + 2);
            mma_f16(acc[2], a, b23);
            mma_f16(acc[3], a, b23 + 2);
        }

        if (c + 1 < C) {
            CP_WAIT0();
            BsW[(c + 1) & 1][bn * 20 + bj] = bpk;
        }
        __syncthreads();
    }

    // epilogue (R11-validated): Es[256][33] + partials alias the smem
    float* Es = (float*)sm;
    float* sp = Es + 8448;
    float* sq = sp + 512;
    int g = lane >> 2, tg = lane & 3;

    {
        int r0 = wm * 16 + g, r1 = r0 + 8;
        float bv0 = bias[r0], bv1 = bias[r1];
#pragma unroll
        for (int u = 0; u < 4; ++u) {
            int n = u * 8 + 2 * tg;
            float v0 = acc[u][0] + bv0, v1 = acc[u][1] + bv0;
            float v2 = acc[u][2] + bv1, v3 = acc[u][3] + bv1;
            if (EPI == 1) {
                size_t gi0 = (size_t)r0 * NPIX + n0 + n;
                size_t gi1 = (size_t)r1 * NPIX + n0 + n;
                float2 q0 = *(const float2*)(res + gi0);
                float2 q1 = *(const float2*)(res + gi1);
                v0 += q0.x; v1 += q0.y; v2 += q1.x; v3 += q1.y;
            }
            Es[r0 * 33 + n] = v0;
            Es[r0 * 33 + n + 1] = v1;
            Es[r1 * 33 + n] = v2;
            Es[r1 * 33 + n + 1] = v3;
        }
    }
    __syncthreads();

    int px = tid & 31, cg = tid >> 5;
    if (EPI == 1) {
        float e[16], s = 0.0f, q = 0.0f;
#pragma unroll
        for (int i = 0; i < 16; ++i) {
            e[i] = Es[(cg * 16 + i) * 33 + px];
            s += e[i];
            q = fmaf(e[i], e[i], q);
        }
        sp[cg * 32 + px] = s;
        sq[cg * 32 + px] = q;
        __syncthreads();
        float ts = 0.0f, tq = 0.0f;
#pragma unroll
        for (int j = 0; j < 16; ++j) {
            ts += sp[j * 32 + px];
            tq += sq[j * 32 + px];
        }
        float mean = ts * (1.0f / DIMC);
        float rstd = rsqrtf(tq * (1.0f / DIMC) - mean * mean + 1e-5f);
#pragma unroll
        for (int i = 0; i < 16; ++i) {
            int cc = cg * 16 + i;
            Y[(size_t)cc * NPIX + n0 + px] = (e[i] - mean) * rstd * lng[cc] + lnb[cc];
        }
    } else {
        float v[16], s = 0.0f, q = 0.0f;
#pragma unroll
        for (int i = 0; i < 16; ++i) {
            v[i] = s1x[(size_t)(cg * 16 + i) * NPIX + n0 + px];
            s += v[i];
            q = fmaf(v[i], v[i], q);
        }
        sp[cg * 32 + px] = s;
        sq[cg * 32 + px] = q;
        __syncthreads();
        float ts = 0.0f, tq = 0.0f;
#pragma unroll
        for (int j = 0; j < 16; ++j) {
            ts += sp[j * 32 + px];
            tq += sq[j * 32 + px];
        }
        float mean = ts * (1.0f / DIMC);
        float rstd = rsqrtf(tq * (1.0f / DIMC) - mean * mean + 1e-5f);
#pragma unroll
        for (int i = 0; i < 16; ++i) {
            int cc = cg * 16 + i;
            y1[(size_t)cc * NPIX + n0 + px] =
                (v[i] - mean) * rstd * s1g[cc] + s1b[cc] + pos[cc] + Es[cc * 33 + px];
        }
        __syncthreads();
        s = 0.0f; q = 0.0f;
#pragma unroll
        for (int i = 0; i < 16; ++i) {
            v[i] = s2x[(size_t)(cg * 16 + i) * NPIX + n0 + px];
            s += v[i];
            q = fmaf(v[i], v[i], q);
        }
        sp[cg * 32 + px] = s;
        sq[cg * 32 + px] = q;
        __syncthreads();
        ts = 0.0f; tq = 0.0f;
#pragma unroll
        for (int j = 0; j < 16; ++j) {
            ts += sp[j * 32 + px];
            tq += sq[j * 32 + px];
        }
        mean = ts * (1.0f / DIMC);
        rstd = rsqrtf(tq * (1.0f / DIMC) - mean * mean + 1e-5f);
#pragma unroll
        for (int i = 0; i < 16; ++i) {
            int cc = cg * 16 + i;
            y2[(size_t)cc * NPIX + n0 + px] =
                (v[i] - mean) * rstd * s2g[cc] + s2b[cc] + pos[cc] + Es[cc * 33 + px];
        }
    }
}

// ---------------------------------------------------------------------------
// Flash attention, fp16 HMMA + MUFU exp2 + ldmatrix (validated R10/R11).
// ---------------------------------------------------------------------------
#define FL_SMEM 37888

__global__ void __launch_bounds__(256, 2)
flash_mma(const __half* __restrict__ Q16, const __half* __restrict__ K16,
          const __half* __restrict__ V16, float* __restrict__ O) {
    extern __shared__ uint32_t fsm[];
    uint32_t* Ks = fsm;               // [2][64][20]
    uint32_t* Vs = fsm + 2560;        // [2][32][36]
    uint32_t* Ps = fsm + 4864;        // [128][36]

    int tid = threadIdx.x;
    int wid = tid >> 5, lane = tid & 31;
    int g = lane >> 2, tg = lane & 3;
    int h = blockIdx.y;
    int n0 = blockIdx.x * 128;
    int r0 = wid * 16 + g, r1 = r0 + 8;

    const __half* Qh = Q16 + (size_t)h * 32 * NPIX;
    const __half* Kh = K16 + (size_t)h * 32 * NPIX;
    const uint32_t* Vhu = (const uint32_t*)(V16 + (size_t)h * 32 * NPIX);

    uint32_t ks_b = s2u(fsm);
    uint32_t vs_b = ks_b + 2560 * 4;
    uint32_t ps_b = ks_b + 4864 * 4;
    uint32_t kfrag = (uint32_t)((lane & 7) + ((lane >> 4) & 1) * 8) * 80
                   + (uint32_t)((lane >> 3) & 1) * 16;
    uint32_t vfrag = (uint32_t)((lane & 7) + ((lane >> 4) & 1) * 8) * 144
                   + (uint32_t)((lane >> 3) & 1) * 16;
    uint32_t pfrag = (uint32_t)(wid * 16 + (lane & 7) + ((lane >> 3) & 1) * 8) * 144
                   + (uint32_t)(lane >> 4) * 16;

    int kkey = tid & 63, kds = tid >> 6;
    int vd = tid >> 4, vslot = tid & 15;

    __half kr[2][4];
    uint2 vr[2];
#pragma unroll
    for (int i = 0; i < 2; ++i) {
        int ds = kds + i * 4;
#pragma unroll
        for (int j = 0; j < 4; ++j)
            kr[i][j] = Kh[(size_t)(ds * 4 + j) * NPIX + kkey];
        vr[i] = *(const uint2*)(Vhu + (size_t)(vd + i * 16) * 2048 + vslot * 2);
    }

    __half* Qsh = (__half*)Ps;
#pragma unroll
    for (int it = 0; it < 4; ++it) {
        int t = tid + it * 256;
        int q4 = t & 31, d = t >> 5;
        uint2 qv = *(const uint2*)(Qh + (size_t)d * NPIX + n0 + q4 * 4);
        const __half* qp = (const __half*)&qv;
        Qsh[(q4 * 4 + 0) * 40 + d] = qp[0];
        Qsh[(q4 * 4 + 1) * 40 + d] = qp[1];
        Qsh[(q4 * 4 + 2) * 40 + d] = qp[2];
        Qsh[(q4 * 4 + 3) * 40 + d] = qp[3];
    }
    __syncthreads();
    uint32_t qa[2][4];
#pragma unroll
    for (int ks = 0; ks < 2; ++ks) {
        int kc = ks * 8 + tg;
        qa[ks][0] = Ps[r0 * 20 + kc];
        qa[ks][1] = Ps[r1 * 20 + kc];
        qa[ks][2] = Ps[r0 * 20 + kc + 4];
        qa[ks][3] = Ps[r1 * 20 + kc + 4];
    }
#pragma unroll
    for (int i = 0; i < 2; ++i) {
        int ds = kds + i * 4;
        *(uint2*)(Ks + kkey * 20 + ds * 2) =
            make_uint2(packhh(kr[i][0], kr[i][1]), packhh(kr[i][2], kr[i][3]));
        *(uint2*)(Vs + (vd + i * 16) * 36 + vslot * 2) = vr[i];
    }
    __syncthreads();

    float m0s = -1e30f, m1s = -1e30f, l0 = 0.0f, l1 = 0.0f;
    float oa[4][4];
#pragma unroll
    for (int u = 0; u < 4; ++u)
#pragma unroll
        for (int e = 0; e < 4; ++e) oa[u][e] = 0.0f;

    for (int kt = 0; kt < 64; ++kt) {
        if (kt + 1 < 64) {
            int mg = (kt + 1) * 64;
#pragma unroll
            for (int i = 0; i < 2; ++i) {
                int ds = kds + i * 4;
#pragma unroll
                for (int j = 0; j < 4; ++j)
                    kr[i][j] = Kh[(size_t)(ds * 4 + j) * NPIX + mg + kkey];
                vr[i] = *(const uint2*)(Vhu + (size_t)(vd + i * 16) * 2048 + (mg >> 1) + vslot * 2);
            }
        }

        uint32_t KsA = ks_b + (kt & 1) * 5120;
        uint32_t VsA = vs_b + (kt & 1) * 4608;

        float sc[8][4];
#pragma unroll
        for (int ns = 0; ns < 8; ++ns)
#pragma unroll
            for (int e = 0; e < 4; ++e) sc[ns][e] = 0.0f;
#pragma unroll
        for (int ks = 0; ks < 2; ++ks) {
#pragma unroll
            for (int nb = 0; nb < 4; ++nb) {
                uint32_t bb[4];
                LDSM4(bb, KsA + nb * 1280 + kfrag + ks * 32);
                mma_f16(sc[2 * nb], qa[ks], bb);
                mma_f16(sc[2 * nb + 1], qa[ks], bb + 2);
            }
        }

        float mx0 = -1e30f, mx1 = -1e30f;
#pragma unroll
        for (int ns = 0; ns < 8; ++ns) {
            mx0 = fmaxf(mx0, fmaxf(sc[ns][0], sc[ns][1]));
            mx1 = fmaxf(mx1, fmaxf(sc[ns][2], sc[ns][3]));
        }
        mx0 = fmaxf(mx0, __shfl_xor_sync(0xffffffffu, mx0, 1));
        mx0 = fmaxf(mx0, __shfl_xor_sync(0xffffffffu, mx0, 2));
        mx1 = fmaxf(mx1, __shfl_xor_sync(0xffffffffu, mx1, 1));
        mx1 = fmaxf(mx1, __shfl_xor_sync(0xffffffffu, mx1, 2));
        float mn0 = fmaxf(m0s, mx0), mn1 = fmaxf(m1s, mx1);
        float c0f = fexp2(m0s - mn0), c1f = fexp2(m1s - mn1);
        float rs0 = 0.0f, rs1 = 0.0f;
#pragma unroll
        for (int ns = 0; ns < 8; ++ns) {
            float p0 = fexp2(sc[ns][0] - mn0);
            float p1 = fexp2(sc[ns][1] - mn0);
            float p2 = fexp2(sc[ns][2] - mn1);
            float p3 = fexp2(sc[ns][3] - mn1);
            rs0 += p0 + p1;
            rs1 += p2 + p3;
            Ps[r0 * 36 + ns * 4 + tg] = packh2(p0, p1);
            Ps[r1 * 36 + ns * 4 + tg] = packh2(p2, p3);
        }
        rs0 += __shfl_xor_sync(0xffffffffu, rs0, 1);
        rs0 += __shfl_xor_sync(0xffffffffu, rs0, 2);
        rs1 += __shfl_xor_sync(0xffffffffu, rs1, 1);
        rs1 += __shfl_xor_sync(0xffffffffu, rs1, 2);
        l0 = l0 * c0f + rs0;
        l1 = l1 * c1f + rs1;
        m0s = mn0; m1s = mn1;
#pragma unroll
        for (int u = 0; u < 4; ++u) {
            oa[u][0] *= c0f; oa[u][1] *= c0f;
            oa[u][2] *= c1f; oa[u][3] *= c1f;
        }
        __syncwarp();

#pragma unroll
        for (int ks = 0; ks < 4; ++ks) {
            uint32_t pa[4], v0[4], v1[4];
            LDSM4(pa, ps_b + pfrag + ks * 32);
            LDSM4(v0, VsA + vfrag + ks * 32);
            LDSM4(v1, VsA + vfrag + 2304 + ks * 32);
            mma_f16(oa[0], pa, v0);
            mma_f16(oa[1], pa, v0 + 2);
            mma_f16(oa[2], pa, v1);
            mma_f16(oa[3], pa, v1 + 2);
        }
        __syncwarp();

        if (kt + 1 < 64) {
            uint32_t* Ksn = Ks + ((kt + 1) & 1) * 1280;
            uint32_t* Vsn = Vs + ((kt + 1) & 1) * 1152;
#pragma unroll
            for (int i = 0; i < 2; ++i) {
                int ds = kds + i * 4;
                *(uint2*)(Ksn + kkey * 20 + ds * 2) =
                    make_uint2(packhh(kr[i][0], kr[i][1]), packhh(kr[i][2], kr[i][3]));
                *(uint2*)(Vsn + (vd + i * 16) * 36 + vslot * 2) = vr[i];
            }
            __syncthreads();
        }
    }

    float il0 = 1.0f / l0, il1 = 1.0f / l1;
#pragma unroll
    for (int ns = 0; ns < 4; ++ns) {
        int d0 = ns * 8 + 2 * tg;
        O[(size_t)(h * 32 + d0) * NPIX + n0 + r0] = oa[ns][0] * il0;
        O[(size_t)(h * 32 + d0 + 1) * NPIX + n0 + r0] = oa[ns][1] * il0;
        O[(size_t)(h * 32 + d0) * NPIX + n0 + r1] = oa[ns][2] * il1;
        O[(size_t)(h * 32 + d0 + 1) * NPIX + n0 + r1] = oa[ns][3] * il1;
    }
}

// ---------------------------------------------------------------------------
extern "C" void kernel_launch(void* const* d_in, const int* in_sizes, int n_in,
                              void* d_out, int out_size) {
    const float* rgb   = (const float*)d_in[0];
    const float* dpt   = (const float*)d_in[1];
    const float* xdpt  = (const float*)d_in[2];
    const float* wq    = (const float*)d_in[3];
    const float* bq    = (const float*)d_in[4];
    const float* wk    = (const float*)d_in[5];
    const float* bk    = (const float*)d_in[6];
    const float* wv    = (const float*)d_in[7];
    const float* bv    = (const float*)d_in[8];
    const float* wo    = (const float*)d_in[9];
    const float* bo    = (const float*)d_in[10];
    const float* ga_rgb = (const float*)d_in[11];
    const float* be_rgb = (const float*)d_in[12];
    const float* ga_dpt = (const float*)d_in[13];
    const float* be_dpt = (const float*)d_in[14];
    const float* ga1   = (const float*)d_in[15];
    const float* be1   = (const float*)d_in[16];
    const float* ga2   = (const float*)d_in[17];
    const float* be2   = (const float*)d_in[18];
    const float* w_mlp1 = (const float*)d_in[19];
    const float* b_mlp1 = (const float*)d_in[20];
    const float* w_mlp2 = (const float*)d_in[21];
    const float* b_mlp2 = (const float*)d_in[22];
    const float* w_de1 = (const float*)d_in[23];
    const float* b_de1 = (const float*)d_in[24];
    const float* w_de2 = (const float*)d_in[25];
    const float* b_de2 = (const float*)d_in[26];
    const float* pos_emb = (const float*)d_in[27];
    const float* scale = (const float*)d_in[28];
    float* out = (float*)d_out;

    float *p_xd, *p_r1, *p_rgbln, *p_dptln, *p_fused, *p_oln;
    __half *p_q16, *p_k16, *p_v16, *p_w16, *p_h16;
    cudaGetSymbolAddress((void**)&p_xd, g_xd);
    cudaGetSymbolAddress((void**)&p_r1, g_r1);
    cudaGetSymbolAddress((void**)&p_rgbln, g_rgbln);
    cudaGetSymbolAddress((void**)&p_dptln, g_dptln);
    cudaGetSymbolAddress((void**)&p_q16, g_q16);
    cudaGetSymbolAddress((void**)&p_k16, g_k16);
    cudaGetSymbolAddress((void**)&p_v16, g_v16);
    cudaGetSymbolAddress((void**)&p_fused, g_fused);
    cudaGetSymbolAddress((void**)&p_oln, g_oln);
    cudaGetSymbolAddress((void**)&p_h16, g_h16);
    cudaGetSymbolAddress((void**)&p_w16, g_w16);

    static bool attr_done = false;
    if (!attr_done) {
        cudaFuncSetAttribute(gemm_mma<2, 1>, cudaFuncAttributeMaxDynamicSharedMemorySize, GEMM_SMEM);
        cudaFuncSetAttribute(gemm_qkv, cudaFuncAttributeMaxDynamicSharedMemorySize, GEMM_SMEM);
        cudaFuncSetAttribute(gemm_ln<0, 0>, cudaFuncAttributeMaxDynamicSharedMemorySize, GLN_SMEM);
        cudaFuncSetAttribute(gemm_ln<1, 0>, cudaFuncAttributeMaxDynamicSharedMemorySize, GLN_SMEM);
        cudaFuncSetAttribute(gemm_ln<1, 1>, cudaFuncAttributeMaxDynamicSharedMemorySize, GLN_SMEM);
        cudaFuncSetAttribute(flash_mma, cudaFuncAttributeMaxDynamicSharedMemorySize, FL_SMEM);
        attr_done = true;
    }

    // weights -> fp16 pool
    cvt_weights<<<dim3(128, 7), 256>>>(w_de2, wq, wk, wv, wo, w_mlp1, w_mlp2, p_w16);

    // depth positional-embedding path
    downsample_kernel<<<16, 256>>>(xdpt, p_xd);
    conv3_kernel<<<256, 256>>>(p_xd, w_de1, b_de1, p_r1);

    // pe GEMM fused with LN(rgb)+pos+pe and LN(dpt)+pos+pe
    gemm_ln<0, 0><<<128, 512, GLN_SMEM>>>(p_w16 + OFF_DE2, p_r1, b_de2, nullptr, nullptr, nullptr,
                                          nullptr, DIMC,
                                          rgb, ga_rgb, be_rgb, dpt, ga_dpt, be_dpt,
                                          pos_emb, p_rgbln, p_dptln);

    // QKV projections
    gemm_qkv<<<dim3(64, 2, 3), 256, GEMM_SMEM>>>(p_w16, bq, bk, bv,
                                                 p_rgbln, p_dptln, p_q16, p_k16, p_v16, scale);

    // flash attention
    flash_mma<<<dim3(32, 8), 256, FL_SMEM>>>(p_q16, p_k16, p_v16, p_fused);

    // output proj + residual + LN1 fused -> oln
    gemm_ln<1, 0><<<128, 512, GLN_SMEM>>>(p_w16 + OFF_O, p_fused, bo, rgb, ga1, be1,
                                          p_oln, DIMC,
                                          nullptr, nullptr, nullptr, nullptr, nullptr,
                                          nullptr, nullptr, nullptr, nullptr);

    // MLP up (exact gelu), fp16 output
    gemm_mma<2, 1><<<dim3(64, 8), 256, GEMM_SMEM>>>(p_w16 + OFF_M1, p_oln, b_mlp1, (void*)p_h16,
                                                    MLPC, DIMC, NPIX);

    // MLP down (fp16 X) + residual + final LN fused -> d_out
    gemm_ln<1, 1><<<128, 512, GLN_SMEM>>>(p_w16 + OFF_M2, p_h16, b_mlp2, p_oln, ga2, be2,
                                          out, MLPC,
                                          nullptr, nullptr, nullptr, nullptr, nullptr,
                                          nullptr, nullptr, nullptr, nullptr);
}

// round 15
// speedup vs baseline: 1.0192x; 1.0013x over previous
#include <cuda_runtime.h>
#include <cuda_fp16.h>
#include <math.h>
#include <stdint.h>

// ---------------------------------------------------------------------------
// B=1, DIM=256, HEADS=8, HD=32, H=W=64 -> N=4096, MLP=1024
// Layout: [C][N] (NCHW flattened), row stride N=4096.
// ---------------------------------------------------------------------------
#define NPIX 4096
#define DIMC 256
#define MLPC 1024

__device__ float g_xd[NPIX];
__device__ float g_r1[DIMC * NPIX];
__device__ float g_rgbln[DIMC * NPIX];
__device__ float g_dptln[DIMC * NPIX];
__device__ __half g_q16[DIMC * NPIX];
__device__ __half g_k16[DIMC * NPIX];
__device__ __half g_v16[DIMC * NPIX];
__device__ float g_fused[DIMC * NPIX];
__device__ float g_oln[DIMC * NPIX];
__device__ float g_h[MLPC * NPIX];

// fp16 weight pool (converted once per launch)
#define OFF_DE2 0
#define OFF_Q   65536
#define OFF_K   131072
#define OFF_V   196608
#define OFF_O   262144
#define OFF_M1  327680
#define OFF_M2  589824
__device__ __half g_w16[851968];

__device__ __forceinline__ float fexp2(float x) {
    float y;
    asm("ex2.approx.f32 %0, %1;" : "=f"(y) : "f"(x));
    return y;
}
__device__ __forceinline__ uint32_t packh2(float a, float b) {
    __half2 h = __floats2half2_rn(a, b);
    return *(uint32_t*)&h;
}
__device__ __forceinline__ uint32_t packhh(__half a, __half b) {
    __half2 h = __halves2half2(a, b);
    return *(uint32_t*)&h;
}
__device__ __forceinline__ uint32_t s2u(const void* p) {
    uint32_t a;
    asm("{ .reg .u64 t; cvta.to.shared.u64 t, %1; cvt.u32.u64 %0, t; }" : "=r"(a) : "l"(p));
    return a;
}
__device__ __forceinline__ void mma_f16(float c[4], const uint32_t a[4], const uint32_t b[2]) {
    asm volatile(
        "mma.sync.aligned.m16n8k16.row.col.f32.f16.f16.f32 "
        "{%0,%1,%2,%3}, {%4,%5,%6,%7}, {%8,%9}, {%0,%1,%2,%3};"
        : "+f"(c[0]), "+f"(c[1]), "+f"(c[2]), "+f"(c[3])
        : "r"(a[0]), "r"(a[1]), "r"(a[2]), "r"(a[3]), "r"(b[0]), "r"(b[1]));
}
#define LDSM4(r, addr) \
    asm volatile("ldmatrix.sync.aligned.m8n8.x4.shared.b16 {%0,%1,%2,%3}, [%4];" \
                 : "=r"((r)[0]), "=r"((r)[1]), "=r"((r)[2]), "=r"((r)[3]) : "r"(addr))
#define CP16(d, s) \
    asm volatile("cp.async.cg.shared.global [%0], [%1], 16;" :: "r"(d), "l"(s))
#define CP_COMMIT() asm volatile("cp.async.commit_group;")
#define CP_WAIT0() asm volatile("cp.async.wait_group 0;" ::: "memory")
#define CP_WAIT1() asm volatile("cp.async.wait_group 1;" ::: "memory")

// ---------------------------------------------------------------------------
// Weight fp32 -> fp16 conversion (once per launch). grid (128, 7).
// ---------------------------------------------------------------------------
__global__ void cvt_weights(const float* __restrict__ de2, const float* __restrict__ q,
                            const float* __restrict__ k, const float* __restrict__ v,
                            const float* __restrict__ o, const float* __restrict__ m1,
                            const float* __restrict__ m2, __half* __restrict__ out) {
    int r = blockIdx.y;
    const float* src;
    __half* dst;
    int n;
    switch (r) {
        case 0: src = de2; dst = out + OFF_DE2; n = 65536; break;
        case 1: src = q;   dst = out + OFF_Q;   n = 65536; break;
        case 2: src = k;   dst = out + OFF_K;   n = 65536; break;
        case 3: src = v;   dst = out + OFF_V;   n = 65536; break;
        case 4: src = o;   dst = out + OFF_O;   n = 65536; break;
        case 5: src = m1;  dst = out + OFF_M1;  n = 262144; break;
        default: src = m2; dst = out + OFF_M2;  n = 262144; break;
    }
    int idx = (blockIdx.x * 256 + threadIdx.x) * 8;
    if (idx >= n) return;
    float4 f0 = *(const float4*)(src + idx);
    float4 f1 = *(const float4*)(src + idx + 4);
    uint4 u;
    u.x = packh2(f0.x, f0.y); u.y = packh2(f0.z, f0.w);
    u.z = packh2(f1.x, f1.y); u.w = packh2(f1.z, f1.w);
    *(uint4*)(dst + idx) = u;
}

// ---------------------------------------------------------------------------
// Bilinear 16x downsample 1024x1024 -> 64x64 (align_corners=False)
// ---------------------------------------------------------------------------
__global__ void downsample_kernel(const float* __restrict__ x, float* __restrict__ xd) {
    int p = blockIdx.x * 256 + threadIdx.x;
    int i = p >> 6, j = p & 63;
    int base = (16 * i + 7) * 1024 + (16 * j + 7);
    xd[p] = 0.25f * (x[base] + x[base + 1] + x[base + 1024] + x[base + 1025]);
}

// conv3x3 (1 in, 256 out) + bias + relu
__global__ void conv3_kernel(const float* __restrict__ xd, const float* __restrict__ w,
                             const float* __restrict__ bias, float* __restrict__ y) {
    __shared__ float s_xd[NPIX];
    int tid = threadIdx.x;
    int o = blockIdx.x;
    for (int e = tid; e < NPIX; e += 256) s_xd[e] = xd[e];
    __syncthreads();
    float wr[9];
#pragma unroll
    for (int t = 0; t < 9; ++t) wr[t] = w[o * 9 + t];
    float bv = bias[o];
    for (int it = 0; it < 16; ++it) {
        int p = tid + it * 256;
        int i = p >> 6, j = p & 63;
        float acc = bv;
#pragma unroll
        for (int di = 0; di < 3; ++di) {
            int ii = i + di - 1;
            if (ii < 0 || ii > 63) continue;
#pragma unroll
            for (int dj = 0; dj < 3; ++dj) {
                int jj = j + dj - 1;
                if (jj < 0 || jj > 63) continue;
                acc = fmaf(wr[di * 3 + dj], s_xd[ii * 64 + jj], acc);
            }
        }
        y[o * NPIX + p] = fmaxf(acc, 0.0f);
    }
}

// ---------------------------------------------------------------------------
// GEMM fp16 m16n8k16, ldmatrix + DEPTH-3 cp.async pipeline.
// Smem: A[3][128 rows x 80B] + B[2][64 rows x 80B] = 40960B.
// A(c+2) issued at iter c; wait_group 1 guarantees A(c+1) before its use.
// B regs prefetched 2 chunks ahead, pre-packed half2 (register-neutral).
// ---------------------------------------------------------------------------
#define GEMM_SMEM 40960

template <int ACT, int OUT16>
__device__ __forceinline__ void gemm_body(
    const __half* __restrict__ W16, const float* __restrict__ X,
    const float* __restrict__ bias, void* __restrict__ Yv,
    int M, int K, int N, int m0, int n0, float oscale) {
    extern __shared__ uint32_t sm[];
    uint32_t sbase = s2u(sm);
    uint32_t Ab_[3] = {sbase, sbase + 10240, sbase + 20480};
    uint32_t Bb_[2] = {sbase + 30720, sbase + 35840};
    uint32_t* BsW[2] = {sm + 7680, sm + 8960};

    int tid = threadIdx.x;
    int wid = tid >> 5, lane = tid & 31;
    int wm = wid >> 1, wn = wid & 1;

    int arow = tid >> 2, aslot = tid & 3;
    int bn = tid & 63, bks = tid >> 6;

    uint32_t a_off = (uint32_t)(wm * 32 + (lane & 7) + ((lane >> 3) & 1) * 8) * 80
                   + (uint32_t)(lane >> 4) * 16;
    uint32_t b_off = (uint32_t)(wn * 32 + (lane & 7) + ((lane >> 4) & 1) * 8) * 80
                   + (uint32_t)((lane >> 3) & 1) * 16;

    const int C = K >> 5;  // >= 8 for all uses
    uint32_t bcur[4], bnext[4];

    // prologue: A chunks 0 and 1 in flight
    CP16(Ab_[0] + arow * 80 + aslot * 16, W16 + (size_t)(m0 + arow) * K + aslot * 8);
    CP16(Ab_[0] + (arow + 64) * 80 + aslot * 16, W16 + (size_t)(m0 + arow + 64) * K + aslot * 8);
    CP_COMMIT();
    CP16(Ab_[1] + arow * 80 + aslot * 16, W16 + (size_t)(m0 + arow) * K + 32 + aslot * 8);
    CP16(Ab_[1] + (arow + 64) * 80 + aslot * 16,
         W16 + (size_t)(m0 + arow + 64) * K + 32 + aslot * 8);
    CP_COMMIT();
#pragma unroll
    for (int j2 = 0; j2 < 4; ++j2)
        bcur[j2] = packh2(X[(size_t)(bks * 8 + 2 * j2) * N + n0 + bn],
                          X[(size_t)(bks * 8 + 2 * j2 + 1) * N + n0 + bn]);

    float acc[2][4][4];
#pragma unroll
    for (int t = 0; t < 2; ++t)
#pragma unroll
        for (int u = 0; u < 4; ++u)
#pragma unroll
            for (int e = 0; e < 4; ++e) acc[t][u][e] = 0.0f;

    CP_WAIT1();  // A0 complete (A1 may be pending)
#pragma unroll
    for (int j2 = 0; j2 < 4; ++j2)
        BsW[0][bn * 20 + bks * 4 + j2] = bcur[j2];
#pragma unroll
    for (int j2 = 0; j2 < 4; ++j2)
        bcur[j2] = packh2(X[(size_t)(32 + bks * 8 + 2 * j2) * N + n0 + bn],
                          X[(size_t)(32 + bks * 8 + 2 * j2 + 1) * N + n0 + bn]);
    __syncthreads();

    for (int c = 0; c < C; ++c) {
        if (c + 2 < C) {
            int k0 = (c + 2) << 5;
            uint32_t ab = Ab_[(c + 2) % 3];
            CP16(ab + arow * 80 + aslot * 16, W16 + (size_t)(m0 + arow) * K + k0 + aslot * 8);
            CP16(ab + (arow + 64) * 80 + aslot * 16,
                 W16 + (size_t)(m0 + arow + 64) * K + k0 + aslot * 8);
            CP_COMMIT();
#pragma unroll
            for (int j2 = 0; j2 < 4; ++j2)
                bnext[j2] = packh2(X[(size_t)(k0 + bks * 8 + 2 * j2) * N + n0 + bn],
                                   X[(size_t)(k0 + bks * 8 + 2 * j2 + 1) * N + n0 + bn]);
        }

        uint32_t Abuf = Ab_[c % 3], Bbuf = Bb_[c & 1];
#pragma unroll
        for (int ks = 0; ks < 2; ++ks) {
            uint32_t a0[4], a1[4], b01[4], b23[4];
            LDSM4(a0, Abuf + a_off + ks * 32);
            LDSM4(a1, Abuf + a_off + 16 * 80 + ks * 32);
            LDSM4(b01, Bbuf + b_off + ks * 32);
            LDSM4(b23, Bbuf + b_off + 16 * 80 + ks * 32);
            mma_f16(acc[0][0], a0, b01);
            mma_f16(acc[0][1], a0, b01 + 2);
            mma_f16(acc[0][2], a0, b23);
            mma_f16(acc[0][3], a0, b23 + 2);
            mma_f16(acc[1][0], a1, b01);
            mma_f16(acc[1][1], a1, b01 + 2);
            mma_f16(acc[1][2], a1, b23);
            mma_f16(acc[1][3], a1, b23 + 2);
        }

        if (c + 1 < C) {
            if (c + 2 < C) { CP_WAIT1(); } else { CP_WAIT0(); }
            uint32_t* bw = BsW[(c + 1) & 1];
#pragma unroll
            for (int j2 = 0; j2 < 4; ++j2)
                bw[bn * 20 + bks * 4 + j2] = bcur[j2];
        }
        __syncthreads();
#pragma unroll
        for (int j2 = 0; j2 < 4; ++j2) bcur[j2] = bnext[j2];
    }

    int g = lane >> 2, tg = lane & 3;
#pragma unroll
    for (int t = 0; t < 2; ++t) {
        int m1 = m0 + wm * 32 + t * 16 + g;
        int m2 = m1 + 8;
        float bv1 = bias[m1], bv2 = bias[m2];
#pragma unroll
        for (int u = 0; u < 4; ++u) {
            int n = n0 + wn * 32 + u * 8 + 2 * tg;
            float v0 = acc[t][u][0] + bv1;
            float v1 = acc[t][u][1] + bv1;
            float v2 = acc[t][u][2] + bv2;
            float v3 = acc[t][u][3] + bv2;
            if (ACT == 2) {
                v0 = 0.5f * v0 * (1.0f + erff(v0 * 0.70710678118654752f));
                v1 = 0.5f * v1 * (1.0f + erff(v1 * 0.70710678118654752f));
                v2 = 0.5f * v2 * (1.0f + erff(v2 * 0.70710678118654752f));
                v3 = 0.5f * v3 * (1.0f + erff(v3 * 0.70710678118654752f));
            }
            if (OUT16) {
                uint32_t* y16 = (uint32_t*)Yv;
                v0 *= oscale; v1 *= oscale; v2 *= oscale; v3 *= oscale;
                y16[(size_t)m1 * (N >> 1) + (n >> 1)] = packh2(v0, v1);
                y16[(size_t)m2 * (N >> 1) + (n >> 1)] = packh2(v2, v3);
            } else {
                float* Y = (float*)Yv;
                *(float2*)(Y + (size_t)m1 * N + n) = make_float2(v0, v1);
                *(float2*)(Y + (size_t)m2 * N + n) = make_float2(v2, v3);
            }
        }
    }
}

template <int ACT, int OUT16>
__global__ void __launch_bounds__(256, 2)
gemm_mma(const __half* __restrict__ W16, const float* __restrict__ X,
         const float* __restrict__ bias, void* __restrict__ Y,
         int M, int K, int N) {
    gemm_body<ACT, OUT16>(W16, X, bias, Y, M, K, N, blockIdx.y * 128, blockIdx.x * 64, 1.0f);
}

__global__ void __launch_bounds__(256, 2)
gemm_qkv(const __half* __restrict__ w16, const float* __restrict__ bq,
         const float* __restrict__ bk, const float* __restrict__ bv,
         const float* __restrict__ xq, const float* __restrict__ xkv,
         __half* __restrict__ q, __half* __restrict__ k, __half* __restrict__ v,
         const float* __restrict__ scale_ptr) {
    int z = blockIdx.z;
    const __half* W = w16 + (z == 0 ? OFF_Q : (z == 1 ? OFF_K : OFF_V));
    const float* B = (z == 0) ? bq : (z == 1) ? bk : bv;
    const float* X = (z == 0) ? xq : xkv;
    __half* Y = (z == 0) ? q : (z == 1) ? k : v;
    float osc = (z == 0) ? (1.4426950408889634f / scale_ptr[0]) : 1.0f;
    gemm_body<0, 1>(W, X, B, (void*)Y, DIMC, DIMC, NPIX,
                    blockIdx.y * 128, blockIdx.x * 64, osc);
}

// ---------------------------------------------------------------------------
// Full-column GEMM (M=256) + fused LayerNorm epilogue — R11 shape (512 thr,
// 16 warps x m16, N-tile 32, grid 128) with the DEPTH-3 cp.async pipeline.
// Smem: A[3][256 x 80B] (61440) + B[2][32 x 80B] (5120) = 66560B.
// Epilogue aliases Es[256][33] fp32 + partial sums (37888B).
// ---------------------------------------------------------------------------
#define GLN_SMEM 66560

template <int EPI>
__global__ void __launch_bounds__(512, 1)
gemm_ln(const __half* __restrict__ W16, const float* __restrict__ X,
        const float* __restrict__ bias, const float* __restrict__ res,
        const float* __restrict__ lng, const float* __restrict__ lnb,
        float* __restrict__ Y, int K,
        const float* __restrict__ s1x, const float* __restrict__ s1g,
        const float* __restrict__ s1b,
        const float* __restrict__ s2x, const float* __restrict__ s2g,
        const float* __restrict__ s2b,
        const float* __restrict__ pos,
        float* __restrict__ y1, float* __restrict__ y2) {
    extern __shared__ uint32_t sm[];
    uint32_t sbase = s2u(sm);
    uint32_t Ab_[3] = {sbase, sbase + 20480, sbase + 40960};
    uint32_t Bb_[2] = {sbase + 61440, sbase + 64000};
    uint32_t* BsW[2] = {sm + 15360, sm + 16000};

    int tid = threadIdx.x;
    int wid = tid >> 5, lane = tid & 31;
    int wm = wid;
    int n0 = blockIdx.x * 32;

    int arow = tid >> 2, aslot = tid & 3;   // rows arow, arow+128
    int bn = tid & 31, bj = tid >> 5;       // pixel, k-pair 0..15

    uint32_t a_off = (uint32_t)(wm * 16 + (lane & 7) + ((lane >> 3) & 1) * 8) * 80
                   + (uint32_t)(lane >> 4) * 16;
    uint32_t b_off = (uint32_t)((lane & 7) + ((lane >> 4) & 1) * 8) * 80
                   + (uint32_t)((lane >> 3) & 1) * 16;

    const int C = K >> 5;  // 8 or 32
    uint32_t bcur, bnext;

    CP16(Ab_[0] + arow * 80 + aslot * 16, W16 + (size_t)arow * K + aslot * 8);
    CP16(Ab_[0] + (arow + 128) * 80 + aslot * 16, W16 + (size_t)(arow + 128) * K + aslot * 8);
    CP_COMMIT();
    CP16(Ab_[1] + arow * 80 + aslot * 16, W16 + (size_t)arow * K + 32 + aslot * 8);
    CP16(Ab_[1] + (arow + 128) * 80 + aslot * 16,
         W16 + (size_t)(arow + 128) * K + 32 + aslot * 8);
    CP_COMMIT();
    bcur = packh2(X[(size_t)(bj * 2) * NPIX + n0 + bn],
                  X[(size_t)(bj * 2 + 1) * NPIX + n0 + bn]);

    float acc[4][4];
#pragma unroll
    for (int u = 0; u < 4; ++u)
#pragma unroll
        for (int e = 0; e < 4; ++e) acc[u][e] = 0.0f;

    CP_WAIT1();  // A0 complete
    BsW[0][bn * 20 + bj] = bcur;
    bcur = packh2(X[(size_t)(32 + bj * 2) * NPIX + n0 + bn],
                  X[(size_t)(32 + bj * 2 + 1) * NPIX + n0 + bn]);
    __syncthreads();

    for (int c = 0; c < C; ++c) {
        if (c + 2 < C) {
            int k0 = (c + 2) << 5;
            uint32_t ab = Ab_[(c + 2) % 3];
            CP16(ab + arow * 80 + aslot * 16, W16 + (size_t)arow * K + k0 + aslot * 8);
            CP16(ab + (arow + 128) * 80 + aslot * 16,
                 W16 + (size_t)(arow + 128) * K + k0 + aslot * 8);
            CP_COMMIT();
            bnext = packh2(X[(size_t)(k0 + bj * 2) * NPIX + n0 + bn],
                           X[(size_t)(k0 + bj * 2 + 1) * NPIX + n0 + bn]);
        }

        uint32_t Abuf = Ab_[c % 3], Bbuf = Bb_[c & 1];
#pragma unroll
        for (int ks = 0; ks < 2; ++ks) {
            uint32_t a[4], b01[4], b23[4];
            LDSM4(a, Abuf + a_off + ks * 32);
            LDSM4(b01, Bbuf + b_off + ks * 32);
            LDSM4(b23, Bbuf + b_off + 16 * 80 + ks * 32);
            mma_f16(acc[0], a, b01);
            mma_f16(acc[1], a, b01 + 2);
            mma_f16(acc[2], a, b23);
            mma_f16(acc[3], a, b23 + 2);
        }

        if (c + 1 < C) {
            if (c + 2 < C) { CP_WAIT1(); } else { CP_WAIT0(); }
            BsW[(c + 1) & 1][bn * 20 + bj] = bcur;
        }
        __syncthreads();
        bcur = bnext;
    }

    // epilogue (R11-validated): Es[256][33] + partials alias the smem
    float* Es = (float*)sm;
    float* sp = Es + 8448;
    float* sq = sp + 512;
    int g = lane >> 2, tg = lane & 3;

    {
        int r0 = wm * 16 + g, r1 = r0 + 8;
        float bv0 = bias[r0], bv1 = bias[r1];
#pragma unroll
        for (int u = 0; u < 4; ++u) {
            int n = u * 8 + 2 * tg;
            float v0 = acc[u][0] + bv0, v1 = acc[u][1] + bv0;
            float v2 = acc[u][2] + bv1, v3 = acc[u][3] + bv1;
            if (EPI == 1) {
                size_t gi0 = (size_t)r0 * NPIX + n0 + n;
                size_t gi1 = (size_t)r1 * NPIX + n0 + n;
                float2 q0 = *(const float2*)(res + gi0);
                float2 q1 = *(const float2*)(res + gi1);
                v0 += q0.x; v1 += q0.y; v2 += q1.x; v3 += q1.y;
            }
            Es[r0 * 33 + n] = v0;
            Es[r0 * 33 + n + 1] = v1;
            Es[r1 * 33 + n] = v2;
            Es[r1 * 33 + n + 1] = v3;
        }
    }
    __syncthreads();

    int px = tid & 31, cg = tid >> 5;
    if (EPI == 1) {
        float e[16], s = 0.0f, q = 0.0f;
#pragma unroll
        for (int i = 0; i < 16; ++i) {
            e[i] = Es[(cg * 16 + i) * 33 + px];
            s += e[i];
            q = fmaf(e[i], e[i], q);
        }
        sp[cg * 32 + px] = s;
        sq[cg * 32 + px] = q;
        __syncthreads();
        float ts = 0.0f, tq = 0.0f;
#pragma unroll
        for (int j = 0; j < 16; ++j) {
            ts += sp[j * 32 + px];
            tq += sq[j * 32 + px];
        }
        float mean = ts * (1.0f / DIMC);
        float rstd = rsqrtf(tq * (1.0f / DIMC) - mean * mean + 1e-5f);
#pragma unroll
        for (int i = 0; i < 16; ++i) {
            int cc = cg * 16 + i;
            Y[(size_t)cc * NPIX + n0 + px] = (e[i] - mean) * rstd * lng[cc] + lnb[cc];
        }
    } else {
        float v[16], s = 0.0f, q = 0.0f;
#pragma unroll
        for (int i = 0; i < 16; ++i) {
            v[i] = s1x[(size_t)(cg * 16 + i) * NPIX + n0 + px];
            s += v[i];
            q = fmaf(v[i], v[i], q);
        }
        sp[cg * 32 + px] = s;
        sq[cg * 32 + px] = q;
        __syncthreads();
        float ts = 0.0f, tq = 0.0f;
#pragma unroll
        for (int j = 0; j < 16; ++j) {
            ts += sp[j * 32 + px];
            tq += sq[j * 32 + px];
        }
        float mean = ts * (1.0f / DIMC);
        float rstd = rsqrtf(tq * (1.0f / DIMC) - mean * mean + 1e-5f);
#pragma unroll
        for (int i = 0; i < 16; ++i) {
            int cc = cg * 16 + i;
            y1[(size_t)cc * NPIX + n0 + px] =
                (v[i] - mean) * rstd * s1g[cc] + s1b[cc] + pos[cc] + Es[cc * 33 + px];
        }
        __syncthreads();
        s = 0.0f; q = 0.0f;
#pragma unroll
        for (int i = 0; i < 16; ++i) {
            v[i] = s2x[(size_t)(cg * 16 + i) * NPIX + n0 + px];
            s += v[i];
            q = fmaf(v[i], v[i], q);
        }
        sp[cg * 32 + px] = s;
        sq[cg * 32 + px] = q;
        __syncthreads();
        ts = 0.0f; tq = 0.0f;
#pragma unroll
        for (int j = 0; j < 16; ++j) {
            ts += sp[j * 32 + px];
            tq += sq[j * 32 + px];
        }
        mean = ts * (1.0f / DIMC);
        rstd = rsqrtf(tq * (1.0f / DIMC) - mean * mean + 1e-5f);
#pragma unroll
        for (int i = 0; i < 16; ++i) {
            int cc = cg * 16 + i;
            y2[(size_t)cc * NPIX + n0 + px] =
                (v[i] - mean) * rstd * s2g[cc] + s2b[cc] + pos[cc] + Es[cc * 33 + px];
        }
    }
}

// ---------------------------------------------------------------------------
// Flash attention, fp16 HMMA + MUFU exp2 + ldmatrix (validated R10/R11).
// ---------------------------------------------------------------------------
#define FL_SMEM 37888

__global__ void __launch_bounds__(256, 2)
flash_mma(const __half* __restrict__ Q16, const __half* __restrict__ K16,
          const __half* __restrict__ V16, float* __restrict__ O) {
    extern __shared__ uint32_t fsm[];
    uint32_t* Ks = fsm;               // [2][64][20]
    uint32_t* Vs = fsm + 2560;        // [2][32][36]
    uint32_t* Ps = fsm + 4864;        // [128][36]

    int tid = threadIdx.x;
    int wid = tid >> 5, lane = tid & 31;
    int g = lane >> 2, tg = lane & 3;
    int h = blockIdx.y;
    int n0 = blockIdx.x * 128;
    int r0 = wid * 16 + g, r1 = r0 + 8;

    const __half* Qh = Q16 + (size_t)h * 32 * NPIX;
    const __half* Kh = K16 + (size_t)h * 32 * NPIX;
    const uint32_t* Vhu = (const uint32_t*)(V16 + (size_t)h * 32 * NPIX);

    uint32_t ks_b = s2u(fsm);
    uint32_t vs_b = ks_b + 2560 * 4;
    uint32_t ps_b = ks_b + 4864 * 4;
    uint32_t kfrag = (uint32_t)((lane & 7) + ((lane >> 4) & 1) * 8) * 80
                   + (uint32_t)((lane >> 3) & 1) * 16;
    uint32_t vfrag = (uint32_t)((lane & 7) + ((lane >> 4) & 1) * 8) * 144
                   + (uint32_t)((lane >> 3) & 1) * 16;
    uint32_t pfrag = (uint32_t)(wid * 16 + (lane & 7) + ((lane >> 3) & 1) * 8) * 144
                   + (uint32_t)(lane >> 4) * 16;

    int kkey = tid & 63, kds = tid >> 6;
    int vd = tid >> 4, vslot = tid & 15;

    __half kr[2][4];
    uint2 vr[2];
#pragma unroll
    for (int i = 0; i < 2; ++i) {
        int ds = kds + i * 4;
#pragma unroll
        for (int j = 0; j < 4; ++j)
            kr[i][j] = Kh[(size_t)(ds * 4 + j) * NPIX + kkey];
        vr[i] = *(const uint2*)(Vhu + (size_t)(vd + i * 16) * 2048 + vslot * 2);
    }

    __half* Qsh = (__half*)Ps;
#pragma unroll
    for (int it = 0; it < 4; ++it) {
        int t = tid + it * 256;
        int q4 = t & 31, d = t >> 5;
        uint2 qv = *(const uint2*)(Qh + (size_t)d * NPIX + n0 + q4 * 4);
        const __half* qp = (const __half*)&qv;
        Qsh[(q4 * 4 + 0) * 40 + d] = qp[0];
        Qsh[(q4 * 4 + 1) * 40 + d] = qp[1];
        Qsh[(q4 * 4 + 2) * 40 + d] = qp[2];
        Qsh[(q4 * 4 + 3) * 40 + d] = qp[3];
    }
    __syncthreads();
    uint32_t qa[2][4];
#pragma unroll
    for (int ks = 0; ks < 2; ++ks) {
        int kc = ks * 8 + tg;
        qa[ks][0] = Ps[r0 * 20 + kc];
        qa[ks][1] = Ps[r1 * 20 + kc];
        qa[ks][2] = Ps[r0 * 20 + kc + 4];
        qa[ks][3] = Ps[r1 * 20 + kc + 4];
    }
#pragma unroll
    for (int i = 0; i < 2; ++i) {
        int ds = kds + i * 4;
        *(uint2*)(Ks + kkey * 20 + ds * 2) =
            make_uint2(packhh(kr[i][0], kr[i][1]), packhh(kr[i][2], kr[i][3]));
        *(uint2*)(Vs + (vd + i * 16) * 36 + vslot * 2) = vr[i];
    }
    __syncthreads();

    float m0s = -1e30f, m1s = -1e30f, l0 = 0.0f, l1 = 0.0f;
    float oa[4][4];
#pragma unroll
    for (int u = 0; u < 4; ++u)
#pragma unroll
        for (int e = 0; e < 4; ++e) oa[u][e] = 0.0f;

    for (int kt = 0; kt < 64; ++kt) {
        if (kt + 1 < 64) {
            int mg = (kt + 1) * 64;
#pragma unroll
            for (int i = 0; i < 2; ++i) {
                int ds = kds + i * 4;
#pragma unroll
                for (int j = 0; j < 4; ++j)
                    kr[i][j] = Kh[(size_t)(ds * 4 + j) * NPIX + mg + kkey];
                vr[i] = *(const uint2*)(Vhu + (size_t)(vd + i * 16) * 2048 + (mg >> 1) + vslot * 2);
            }
        }

        uint32_t KsA = ks_b + (kt & 1) * 5120;
        uint32_t VsA = vs_b + (kt & 1) * 4608;

        float sc[8][4];
#pragma unroll
        for (int ns = 0; ns < 8; ++ns)
#pragma unroll
            for (int e = 0; e < 4; ++e) sc[ns][e] = 0.0f;
#pragma unroll
        for (int ks = 0; ks < 2; ++ks) {
#pragma unroll
            for (int nb = 0; nb < 4; ++nb) {
                uint32_t bb[4];
                LDSM4(bb, KsA + nb * 1280 + kfrag + ks * 32);
                mma_f16(sc[2 * nb], qa[ks], bb);
                mma_f16(sc[2 * nb + 1], qa[ks], bb + 2);
            }
        }

        float mx0 = -1e30f, mx1 = -1e30f;
#pragma unroll
        for (int ns = 0; ns < 8; ++ns) {
            mx0 = fmaxf(mx0, fmaxf(sc[ns][0], sc[ns][1]));
            mx1 = fmaxf(mx1, fmaxf(sc[ns][2], sc[ns][3]));
        }
        mx0 = fmaxf(mx0, __shfl_xor_sync(0xffffffffu, mx0, 1));
        mx0 = fmaxf(mx0, __shfl_xor_sync(0xffffffffu, mx0, 2));
        mx1 = fmaxf(mx1, __shfl_xor_sync(0xffffffffu, mx1, 1));
        mx1 = fmaxf(mx1, __shfl_xor_sync(0xffffffffu, mx1, 2));
        float mn0 = fmaxf(m0s, mx0), mn1 = fmaxf(m1s, mx1);
        float c0f = fexp2(m0s - mn0), c1f = fexp2(m1s - mn1);
        float rs0 = 0.0f, rs1 = 0.0f;
#pragma unroll
        for (int ns = 0; ns < 8; ++ns) {
            float p0 = fexp2(sc[ns][0] - mn0);
            float p1 = fexp2(sc[ns][1] - mn0);
            float p2 = fexp2(sc[ns][2] - mn1);
            float p3 = fexp2(sc[ns][3] - mn1);
            rs0 += p0 + p1;
            rs1 += p2 + p3;
            Ps[r0 * 36 + ns * 4 + tg] = packh2(p0, p1);
            Ps[r1 * 36 + ns * 4 + tg] = packh2(p2, p3);
        }
        rs0 += __shfl_xor_sync(0xffffffffu, rs0, 1);
        rs0 += __shfl_xor_sync(0xffffffffu, rs0, 2);
        rs1 += __shfl_xor_sync(0xffffffffu, rs1, 1);
        rs1 += __shfl_xor_sync(0xffffffffu, rs1, 2);
        l0 = l0 * c0f + rs0;
        l1 = l1 * c1f + rs1;
        m0s = mn0; m1s = mn1;
#pragma unroll
        for (int u = 0; u < 4; ++u) {
            oa[u][0] *= c0f; oa[u][1] *= c0f;
            oa[u][2] *= c1f; oa[u][3] *= c1f;
        }
        __syncwarp();

#pragma unroll
        for (int ks = 0; ks < 4; ++ks) {
            uint32_t pa[4], v0[4], v1[4];
            LDSM4(pa, ps_b + pfrag + ks * 32);
            LDSM4(v0, VsA + vfrag + ks * 32);
            LDSM4(v1, VsA + vfrag + 2304 + ks * 32);
            mma_f16(oa[0], pa, v0);
            mma_f16(oa[1], pa, v0 + 2);
            mma_f16(oa[2], pa, v1);
            mma_f16(oa[3], pa, v1 + 2);
        }
        __syncwarp();

        if (kt + 1 < 64) {
            uint32_t* Ksn = Ks + ((kt + 1) & 1) * 1280;
            uint32_t* Vsn = Vs + ((kt + 1) & 1) * 1152;
#pragma unroll
            for (int i = 0; i < 2; ++i) {
                int ds = kds + i * 4;
                *(uint2*)(Ksn + kkey * 20 + ds * 2) =
                    make_uint2(packhh(kr[i][0], kr[i][1]), packhh(kr[i][2], kr[i][3]));
                *(uint2*)(Vsn + (vd + i * 16) * 36 + vslot * 2) = vr[i];
            }
            __syncthreads();
        }
    }

    float il0 = 1.0f / l0, il1 = 1.0f / l1;
#pragma unroll
    for (int ns = 0; ns < 4; ++ns) {
        int d0 = ns * 8 + 2 * tg;
        O[(size_t)(h * 32 + d0) * NPIX + n0 + r0] = oa[ns][0] * il0;
        O[(size_t)(h * 32 + d0 + 1) * NPIX + n0 + r0] = oa[ns][1] * il0;
        O[(size_t)(h * 32 + d0) * NPIX + n0 + r1] = oa[ns][2] * il1;
        O[(size_t)(h * 32 + d0 + 1) * NPIX + n0 + r1] = oa[ns][3] * il1;
    }
}

// ---------------------------------------------------------------------------
extern "C" void kernel_launch(void* const* d_in, const int* in_sizes, int n_in,
                              void* d_out, int out_size) {
    const float* rgb   = (const float*)d_in[0];
    const float* dpt   = (const float*)d_in[1];
    const float* xdpt  = (const float*)d_in[2];
    const float* wq    = (const float*)d_in[3];
    const float* bq    = (const float*)d_in[4];
    const float* wk    = (const float*)d_in[5];
    const float* bk    = (const float*)d_in[6];
    const float* wv    = (const float*)d_in[7];
    const float* bv    = (const float*)d_in[8];
    const float* wo    = (const float*)d_in[9];
    const float* bo    = (const float*)d_in[10];
    const float* ga_rgb = (const float*)d_in[11];
    const float* be_rgb = (const float*)d_in[12];
    const float* ga_dpt = (const float*)d_in[13];
    const float* be_dpt = (const float*)d_in[14];
    const float* ga1   = (const float*)d_in[15];
    const float* be1   = (const float*)d_in[16];
    const float* ga2   = (const float*)d_in[17];
    const float* be2   = (const float*)d_in[18];
    const float* w_mlp1 = (const float*)d_in[19];
    const float* b_mlp1 = (const float*)d_in[20];
    const float* w_mlp2 = (const float*)d_in[21];
    const float* b_mlp2 = (const float*)d_in[22];
    const float* w_de1 = (const float*)d_in[23];
    const float* b_de1 = (const float*)d_in[24];
    const float* w_de2 = (const float*)d_in[25];
    const float* b_de2 = (const float*)d_in[26];
    const float* pos_emb = (const float*)d_in[27];
    const float* scale = (const float*)d_in[28];
    float* out = (float*)d_out;

    float *p_xd, *p_r1, *p_rgbln, *p_dptln, *p_fused, *p_oln, *p_h;
    __half *p_q16, *p_k16, *p_v16, *p_w16;
    cudaGetSymbolAddress((void**)&p_xd, g_xd);
    cudaGetSymbolAddress((void**)&p_r1, g_r1);
    cudaGetSymbolAddress((void**)&p_rgbln, g_rgbln);
    cudaGetSymbolAddress((void**)&p_dptln, g_dptln);
    cudaGetSymbolAddress((void**)&p_q16, g_q16);
    cudaGetSymbolAddress((void**)&p_k16, g_k16);
    cudaGetSymbolAddress((void**)&p_v16, g_v16);
    cudaGetSymbolAddress((void**)&p_fused, g_fused);
    cudaGetSymbolAddress((void**)&p_oln, g_oln);
    cudaGetSymbolAddress((void**)&p_h, g_h);
    cudaGetSymbolAddress((void**)&p_w16, g_w16);

    static bool attr_done = false;
    if (!attr_done) {
        cudaFuncSetAttribute(gemm_mma<2, 0>, cudaFuncAttributeMaxDynamicSharedMemorySize, GEMM_SMEM);
        cudaFuncSetAttribute(gemm_qkv, cudaFuncAttributeMaxDynamicSharedMemorySize, GEMM_SMEM);
        cudaFuncSetAttribute(gemm_ln<0>, cudaFuncAttributeMaxDynamicSharedMemorySize, GLN_SMEM);
        cudaFuncSetAttribute(gemm_ln<1>, cudaFuncAttributeMaxDynamicSharedMemorySize, GLN_SMEM);
        cudaFuncSetAttribute(flash_mma, cudaFuncAttributeMaxDynamicSharedMemorySize, FL_SMEM);
        attr_done = true;
    }

    // weights -> fp16 pool
    cvt_weights<<<dim3(128, 7), 256>>>(w_de2, wq, wk, wv, wo, w_mlp1, w_mlp2, p_w16);

    // depth positional-embedding path
    downsample_kernel<<<16, 256>>>(xdpt, p_xd);
    conv3_kernel<<<256, 256>>>(p_xd, w_de1, b_de1, p_r1);

    // pe GEMM fused with LN(rgb)+pos+pe and LN(dpt)+pos+pe
    gemm_ln<0><<<128, 512, GLN_SMEM>>>(p_w16 + OFF_DE2, p_r1, b_de2, nullptr, nullptr, nullptr,
                                       nullptr, DIMC,
                                       rgb, ga_rgb, be_rgb, dpt, ga_dpt, be_dpt,
                                       pos_emb, p_rgbln, p_dptln);

    // QKV projections
    gemm_qkv<<<dim3(64, 2, 3), 256, GEMM_SMEM>>>(p_w16, bq, bk, bv,
                                                 p_rgbln, p_dptln, p_q16, p_k16, p_v16, scale);

    // flash attention
    flash_mma<<<dim3(32, 8), 256, FL_SMEM>>>(p_q16, p_k16, p_v16, p_fused);

    // output proj + residual + LN1 fused -> oln
    gemm_ln<1><<<128, 512, GLN_SMEM>>>(p_w16 + OFF_O, p_fused, bo, rgb, ga1, be1,
                                       p_oln, DIMC,
                                       nullptr, nullptr, nullptr, nullptr, nullptr,
                                       nullptr, nullptr, nullptr, nullptr);

    // MLP up (exact gelu), fp32 output (h16 reverted per R14 A/B evidence)
    gemm_mma<2, 0><<<dim3(64, 8), 256, GEMM_SMEM>>>(p_w16 + OFF_M1, p_oln, b_mlp1, (void*)p_h,
                                                    MLPC, DIMC, NPIX);

    // MLP down + residual + final LN fused -> d_out
    gemm_ln<1><<<128, 512, GLN_SMEM>>>(p_w16 + OFF_M2, p_h, b_mlp2, p_oln, ga2, be2,
                                       out, MLPC,
                                       nullptr, nullptr, nullptr, nullptr, nullptr,
                                       nullptr, nullptr, nullptr, nullptr);
}

// round 16
// speedup vs baseline: 1.1147x; 1.0937x over previous
#include <cuda_runtime.h>
#include <cuda_fp16.h>
#include <math.h>
#include <stdint.h>

// ---------------------------------------------------------------------------
// B=1, DIM=256, HEADS=8, HD=32, H=W=64 -> N=4096, MLP=1024
// Layout: [C][N] (NCHW flattened), row stride N=4096.
// ---------------------------------------------------------------------------
#define NPIX 4096
#define DIMC 256
#define MLPC 1024

__device__ float g_xd[NPIX];
__device__ float g_r1[DIMC * NPIX];
__device__ float g_rgbln[DIMC * NPIX];
__device__ float g_dptln[DIMC * NPIX];
__device__ __half g_q16[DIMC * NPIX];
__device__ __half g_k16[DIMC * NPIX];
__device__ __half g_v16[DIMC * NPIX];
__device__ float g_fused[DIMC * NPIX];
__device__ float g_oln[DIMC * NPIX];
__device__ float g_h[MLPC * NPIX];

// fp16 weight pool (converted once per launch)
#define OFF_DE2 0
#define OFF_Q   65536
#define OFF_K   131072
#define OFF_V   196608
#define OFF_O   262144
#define OFF_M1  327680
#define OFF_M2  589824
__device__ __half g_w16[851968];

__device__ __forceinline__ float fexp2(float x) {
    float y;
    asm("ex2.approx.f32 %0, %1;" : "=f"(y) : "f"(x));
    return y;
}
__device__ __forceinline__ uint32_t packh2(float a, float b) {
    __half2 h = __floats2half2_rn(a, b);
    return *(uint32_t*)&h;
}
__device__ __forceinline__ uint32_t packhh(__half a, __half b) {
    __half2 h = __halves2half2(a, b);
    return *(uint32_t*)&h;
}
__device__ __forceinline__ uint32_t s2u(const void* p) {
    uint32_t a;
    asm("{ .reg .u64 t; cvta.to.shared.u64 t, %1; cvt.u32.u64 %0, t; }" : "=r"(a) : "l"(p));
    return a;
}
__device__ __forceinline__ void mma_f16(float c[4], const uint32_t a[4], const uint32_t b[2]) {
    asm volatile(
        "mma.sync.aligned.m16n8k16.row.col.f32.f16.f16.f32 "
        "{%0,%1,%2,%3}, {%4,%5,%6,%7}, {%8,%9}, {%0,%1,%2,%3};"
        : "+f"(c[0]), "+f"(c[1]), "+f"(c[2]), "+f"(c[3])
        : "r"(a[0]), "r"(a[1]), "r"(a[2]), "r"(a[3]), "r"(b[0]), "r"(b[1]));
}
#define LDSM4(r, addr) \
    asm volatile("ldmatrix.sync.aligned.m8n8.x4.shared.b16 {%0,%1,%2,%3}, [%4];" \
                 : "=r"((r)[0]), "=r"((r)[1]), "=r"((r)[2]), "=r"((r)[3]) : "r"(addr))
#define CP16(d, s) \
    asm volatile("cp.async.cg.shared.global [%0], [%1], 16;" :: "r"(d), "l"(s))
#define CP_COMMIT() asm volatile("cp.async.commit_group;")
#define CP_WAIT0() asm volatile("cp.async.wait_group 0;" ::: "memory")

// ---------------------------------------------------------------------------
// Weight fp32 -> fp16 conversion (once per launch). grid (128, 7).
// ---------------------------------------------------------------------------
__global__ void cvt_weights(const float* __restrict__ de2, const float* __restrict__ q,
                            const float* __restrict__ k, const float* __restrict__ v,
                            const float* __restrict__ o, const float* __restrict__ m1,
                            const float* __restrict__ m2, __half* __restrict__ out) {
    int r = blockIdx.y;
    const float* src;
    __half* dst;
    int n;
    switch (r) {
        case 0: src = de2; dst = out + OFF_DE2; n = 65536; break;
        case 1: src = q;   dst = out + OFF_Q;   n = 65536; break;
        case 2: src = k;   dst = out + OFF_K;   n = 65536; break;
        case 3: src = v;   dst = out + OFF_V;   n = 65536; break;
        case 4: src = o;   dst = out + OFF_O;   n = 65536; break;
        case 5: src = m1;  dst = out + OFF_M1;  n = 262144; break;
        default: src = m2; dst = out + OFF_M2;  n = 262144; break;
    }
    int idx = (blockIdx.x * 256 + threadIdx.x) * 8;
    if (idx >= n) return;
    float4 f0 = *(const float4*)(src + idx);
    float4 f1 = *(const float4*)(src + idx + 4);
    uint4 u;
    u.x = packh2(f0.x, f0.y); u.y = packh2(f0.z, f0.w);
    u.z = packh2(f1.x, f1.y); u.w = packh2(f1.z, f1.w);
    *(uint4*)(dst + idx) = u;
}

// ---------------------------------------------------------------------------
// Bilinear 16x downsample 1024x1024 -> 64x64 (align_corners=False)
// ---------------------------------------------------------------------------
__global__ void downsample_kernel(const float* __restrict__ x, float* __restrict__ xd) {
    int p = blockIdx.x * 256 + threadIdx.x;
    int i = p >> 6, j = p & 63;
    int base = (16 * i + 7) * 1024 + (16 * j + 7);
    xd[p] = 0.25f * (x[base] + x[base + 1] + x[base + 1024] + x[base + 1025]);
}

// conv3x3 (1 in, 256 out) + bias + relu
__global__ void conv3_kernel(const float* __restrict__ xd, const float* __restrict__ w,
                             const float* __restrict__ bias, float* __restrict__ y) {
    __shared__ float s_xd[NPIX];
    int tid = threadIdx.x;
    int o = blockIdx.x;
    for (int e = tid; e < NPIX; e += 256) s_xd[e] = xd[e];
    __syncthreads();
    float wr[9];
#pragma unroll
    for (int t = 0; t < 9; ++t) wr[t] = w[o * 9 + t];
    float bv = bias[o];
    for (int it = 0; it < 16; ++it) {
        int p = tid + it * 256;
        int i = p >> 6, j = p & 63;
        float acc = bv;
#pragma unroll
        for (int di = 0; di < 3; ++di) {
            int ii = i + di - 1;
            if (ii < 0 || ii > 63) continue;
#pragma unroll
            for (int dj = 0; dj < 3; ++dj) {
                int jj = j + dj - 1;
                if (jj < 0 || jj > 63) continue;
                acc = fmaf(wr[di * 3 + dj], s_xd[ii * 64 + jj], acc);
            }
        }
        y[o * NPIX + p] = fmaxf(acc, 0.0f);
    }
}

// ---------------------------------------------------------------------------
// GEMM fp16 m16n8k16, ldmatrix + cp.async, depth-2 (exact R9/R11 proven form).
// ---------------------------------------------------------------------------
#define GEMM_SMEM 30720

template <int ACT, int OUT16>
__device__ __forceinline__ void gemm_body(
    const __half* __restrict__ W16, const float* __restrict__ X,
    const float* __restrict__ bias, void* __restrict__ Yv,
    int M, int K, int N, int m0, int n0, float oscale) {
    extern __shared__ uint32_t sm[];
    uint32_t sbase = s2u(sm);
    uint32_t Ab_[2] = {sbase, sbase + 10240};
    uint32_t Bb_[2] = {sbase + 20480, sbase + 25600};
    uint32_t* BsW[2] = {sm + 5120, sm + 6400};

    int tid = threadIdx.x;
    int wid = tid >> 5, lane = tid & 31;
    int wm = wid >> 1, wn = wid & 1;

    int arow = tid >> 2, aslot = tid & 3;
    int bn = tid & 63, bks = tid >> 6;

    uint32_t a_off = (uint32_t)(wm * 32 + (lane & 7) + ((lane >> 3) & 1) * 8) * 80
                   + (uint32_t)(lane >> 4) * 16;
    uint32_t b_off = (uint32_t)(wn * 32 + (lane & 7) + ((lane >> 4) & 1) * 8) * 80
                   + (uint32_t)((lane >> 3) & 1) * 16;

    const int C = K >> 5;
    float br[8];

    CP16(Ab_[0] + arow * 80 + aslot * 16, W16 + (size_t)(m0 + arow) * K + aslot * 8);
    CP16(Ab_[0] + (arow + 64) * 80 + aslot * 16, W16 + (size_t)(m0 + arow + 64) * K + aslot * 8);
    CP_COMMIT();
#pragma unroll
    for (int j = 0; j < 8; ++j)
        br[j] = X[(size_t)(bks * 8 + j) * N + n0 + bn];

    float acc[2][4][4];
#pragma unroll
    for (int t = 0; t < 2; ++t)
#pragma unroll
        for (int u = 0; u < 4; ++u)
#pragma unroll
            for (int e = 0; e < 4; ++e) acc[t][u][e] = 0.0f;

#pragma unroll
    for (int j2 = 0; j2 < 4; ++j2)
        BsW[0][bn * 20 + bks * 4 + j2] = packh2(br[2 * j2], br[2 * j2 + 1]);
    CP_WAIT0();
    __syncthreads();

    for (int c = 0; c < C; ++c) {
        if (c + 1 < C) {
            int k0 = (c + 1) << 5;
            uint32_t ab = Ab_[(c + 1) & 1];
            CP16(ab + arow * 80 + aslot * 16, W16 + (size_t)(m0 + arow) * K + k0 + aslot * 8);
            CP16(ab + (arow + 64) * 80 + aslot * 16,
                 W16 + (size_t)(m0 + arow + 64) * K + k0 + aslot * 8);
            CP_COMMIT();
#pragma unroll
            for (int j = 0; j < 8; ++j)
                br[j] = X[(size_t)(k0 + bks * 8 + j) * N + n0 + bn];
        }

        uint32_t Abuf = Ab_[c & 1], Bbuf = Bb_[c & 1];
#pragma unroll
        for (int ks = 0; ks < 2; ++ks) {
            uint32_t a0[4], a1[4], b01[4], b23[4];
            LDSM4(a0, Abuf + a_off + ks * 32);
            LDSM4(a1, Abuf + a_off + 16 * 80 + ks * 32);
            LDSM4(b01, Bbuf + b_off + ks * 32);
            LDSM4(b23, Bbuf + b_off + 16 * 80 + ks * 32);
            mma_f16(acc[0][0], a0, b01);
            mma_f16(acc[0][1], a0, b01 + 2);
            mma_f16(acc[0][2], a0, b23);
            mma_f16(acc[0][3], a0, b23 + 2);
            mma_f16(acc[1][0], a1, b01);
            mma_f16(acc[1][1], a1, b01 + 2);
            mma_f16(acc[1][2], a1, b23);
            mma_f16(acc[1][3], a1, b23 + 2);
        }

        if (c + 1 < C) {
            CP_WAIT0();
            uint32_t* bw = BsW[(c + 1) & 1];
#pragma unroll
            for (int j2 = 0; j2 < 4; ++j2)
                bw[bn * 20 + bks * 4 + j2] = packh2(br[2 * j2], br[2 * j2 + 1]);
        }
        __syncthreads();
    }

    int g = lane >> 2, tg = lane & 3;
#pragma unroll
    for (int t = 0; t < 2; ++t) {
        int m1 = m0 + wm * 32 + t * 16 + g;
        int m2 = m1 + 8;
        float bv1 = bias[m1], bv2 = bias[m2];
#pragma unroll
        for (int u = 0; u < 4; ++u) {
            int n = n0 + wn * 32 + u * 8 + 2 * tg;
            float v0 = acc[t][u][0] + bv1;
            float v1 = acc[t][u][1] + bv1;
            float v2 = acc[t][u][2] + bv2;
            float v3 = acc[t][u][3] + bv2;
            if (ACT == 2) {
                v0 = 0.5f * v0 * (1.0f + erff(v0 * 0.70710678118654752f));
                v1 = 0.5f * v1 * (1.0f + erff(v1 * 0.70710678118654752f));
                v2 = 0.5f * v2 * (1.0f + erff(v2 * 0.70710678118654752f));
                v3 = 0.5f * v3 * (1.0f + erff(v3 * 0.70710678118654752f));
            }
            if (OUT16) {
                uint32_t* y16 = (uint32_t*)Yv;
                v0 *= oscale; v1 *= oscale; v2 *= oscale; v3 *= oscale;
                y16[(size_t)m1 * (N >> 1) + (n >> 1)] = packh2(v0, v1);
                y16[(size_t)m2 * (N >> 1) + (n >> 1)] = packh2(v2, v3);
            } else {
                float* Y = (float*)Yv;
                *(float2*)(Y + (size_t)m1 * N + n) = make_float2(v0, v1);
                *(float2*)(Y + (size_t)m2 * N + n) = make_float2(v2, v3);
            }
        }
    }
}

template <int ACT, int OUT16>
__global__ void __launch_bounds__(256, 2)
gemm_mma(const __half* __restrict__ W16, const float* __restrict__ X,
         const float* __restrict__ bias, void* __restrict__ Y,
         int M, int K, int N) {
    gemm_body<ACT, OUT16>(W16, X, bias, Y, M, K, N, blockIdx.y * 128, blockIdx.x * 64, 1.0f);
}

__global__ void __launch_bounds__(256, 2)
gemm_qkv(const __half* __restrict__ w16, const float* __restrict__ bq,
         const float* __restrict__ bk, const float* __restrict__ bv,
         const float* __restrict__ xq, const float* __restrict__ xkv,
         __half* __restrict__ q, __half* __restrict__ k, __half* __restrict__ v,
         const float* __restrict__ scale_ptr) {
    int z = blockIdx.z;
    const __half* W = w16 + (z == 0 ? OFF_Q : (z == 1 ? OFF_K : OFF_V));
    const float* B = (z == 0) ? bq : (z == 1) ? bk : bv;
    const float* X = (z == 0) ? xq : xkv;
    __half* Y = (z == 0) ? q : (z == 1) ? k : v;
    float osc = (z == 0) ? (1.4426950408889634f / scale_ptr[0]) : 1.0f;
    gemm_body<0, 1>(W, X, B, (void*)Y, DIMC, DIMC, NPIX,
                    blockIdx.y * 128, blockIdx.x * 64, osc);
}

// ---------------------------------------------------------------------------
// Full-column GEMM (M=256) + fused LayerNorm epilogue — exact R11 form
// (512 thr = 16 warps x m16, N-tile 32, grid 128, depth-2; best measured).
// Smem u32 (46080B): A[2][256][20], B[2][32][20]; epilogue Es[256][33]+sums.
// ---------------------------------------------------------------------------
#define GLN_SMEM 46080

template <int EPI>
__global__ void __launch_bounds__(512, 1)
gemm_ln(const __half* __restrict__ W16, const float* __restrict__ X,
        const float* __restrict__ bias, const float* __restrict__ res,
        const float* __restrict__ lng, const float* __restrict__ lnb,
        float* __restrict__ Y, int K,
        const float* __restrict__ s1x, const float* __restrict__ s1g,
        const float* __restrict__ s1b,
        const float* __restrict__ s2x, const float* __restrict__ s2g,
        const float* __restrict__ s2b,
        const float* __restrict__ pos,
        float* __restrict__ y1, float* __restrict__ y2) {
    extern __shared__ uint32_t sm[];
    uint32_t sbase = s2u(sm);
    uint32_t Ab_[2] = {sbase, sbase + 20480};
    uint32_t Bb_[2] = {sbase + 40960, sbase + 43520};
    uint32_t* BsW[2] = {sm + 10240, sm + 10880};

    int tid = threadIdx.x;
    int wid = tid >> 5, lane = tid & 31;
    int wm = wid;
    int n0 = blockIdx.x * 32;

    int arow = tid >> 2, aslot = tid & 3;
    int bn = tid & 31, bj = tid >> 5;

    uint32_t a_off = (uint32_t)(wm * 16 + (lane & 7) + ((lane >> 3) & 1) * 8) * 80
                   + (uint32_t)(lane >> 4) * 16;
    uint32_t b_off = (uint32_t)((lane & 7) + ((lane >> 4) & 1) * 8) * 80
                   + (uint32_t)((lane >> 3) & 1) * 16;

    const int C = K >> 5;
    uint32_t bpk;

    CP16(Ab_[0] + arow * 80 + aslot * 16, W16 + (size_t)arow * K + aslot * 8);
    CP16(Ab_[0] + (arow + 128) * 80 + aslot * 16, W16 + (size_t)(arow + 128) * K + aslot * 8);
    CP_COMMIT();
    {
        int kk = bj * 2;
        bpk = packh2(X[(size_t)kk * NPIX + n0 + bn], X[(size_t)(kk + 1) * NPIX + n0 + bn]);
    }

    float acc[4][4];
#pragma unroll
    for (int u = 0; u < 4; ++u)
#pragma unroll
        for (int e = 0; e < 4; ++e) acc[u][e] = 0.0f;

    BsW[0][bn * 20 + bj] = bpk;
    CP_WAIT0();
    __syncthreads();

    for (int c = 0; c < C; ++c) {
        if (c + 1 < C) {
            int k0 = (c + 1) << 5;
            uint32_t ab = Ab_[(c + 1) & 1];
            CP16(ab + arow * 80 + aslot * 16, W16 + (size_t)arow * K + k0 + aslot * 8);
            CP16(ab + (arow + 128) * 80 + aslot * 16,
                 W16 + (size_t)(arow + 128) * K + k0 + aslot * 8);
            CP_COMMIT();
            int kk = k0 + bj * 2;
            bpk = packh2(X[(size_t)kk * NPIX + n0 + bn], X[(size_t)(kk + 1) * NPIX + n0 + bn]);
        }

        uint32_t Abuf = Ab_[c & 1], Bbuf = Bb_[c & 1];
#pragma unroll
        for (int ks = 0; ks < 2; ++ks) {
            uint32_t a[4], b01[4], b23[4];
            LDSM4(a, Abuf + a_off + ks * 32);
            LDSM4(b01, Bbuf + b_off + ks * 32);
            LDSM4(b23, Bbuf + b_off + 16 * 80 + ks * 32);
            mma_f16(acc[0], a, b01);
            mma_f16(acc[1], a, b01 + 2);
            mma_f16(acc[2], a, b23);
            mma_f16(acc[3], a, b23 + 2);
        }

        if (c + 1 < C) {
            CP_WAIT0();
            BsW[(c + 1) & 1][bn * 20 + bj] = bpk;
        }
        __syncthreads();
    }

    float* Es = (float*)sm;
    float* sp = Es + 8448;
    float* sq = sp + 512;
    int g = lane >> 2, tg = lane & 3;

    {
        int r0 = wm * 16 + g, r1 = r0 + 8;
        float bv0 = bias[r0], bv1 = bias[r1];
#pragma unroll
        for (int u = 0; u < 4; ++u) {
            int n = u * 8 + 2 * tg;
            float v0 = acc[u][0] + bv0, v1 = acc[u][1] + bv0;
            float v2 = acc[u][2] + bv1, v3 = acc[u][3] + bv1;
            if (EPI == 1) {
                size_t gi0 = (size_t)r0 * NPIX + n0 + n;
                size_t gi1 = (size_t)r1 * NPIX + n0 + n;
                float2 q0 = *(const float2*)(res + gi0);
                float2 q1 = *(const float2*)(res + gi1);
                v0 += q0.x; v1 += q0.y; v2 += q1.x; v3 += q1.y;
            }
            Es[r0 * 33 + n] = v0;
            Es[r0 * 33 + n + 1] = v1;
            Es[r1 * 33 + n] = v2;
            Es[r1 * 33 + n + 1] = v3;
        }
    }
    __syncthreads();

    int px = tid & 31, cg = tid >> 5;
    if (EPI == 1) {
        float e[16], s = 0.0f, q = 0.0f;
#pragma unroll
        for (int i = 0; i < 16; ++i) {
            e[i] = Es[(cg * 16 + i) * 33 + px];
            s += e[i];
            q = fmaf(e[i], e[i], q);
        }
        sp[cg * 32 + px] = s;
        sq[cg * 32 + px] = q;
        __syncthreads();
        float ts = 0.0f, tq = 0.0f;
#pragma unroll
        for (int j = 0; j < 16; ++j) {
            ts += sp[j * 32 + px];
            tq += sq[j * 32 + px];
        }
        float mean = ts * (1.0f / DIMC);
        float rstd = rsqrtf(tq * (1.0f / DIMC) - mean * mean + 1e-5f);
#pragma unroll
        for (int i = 0; i < 16; ++i) {
            int cc = cg * 16 + i;
            Y[(size_t)cc * NPIX + n0 + px] = (e[i] - mean) * rstd * lng[cc] + lnb[cc];
        }
    } else {
        float v[16], s = 0.0f, q = 0.0f;
#pragma unroll
        for (int i = 0; i < 16; ++i) {
            v[i] = s1x[(size_t)(cg * 16 + i) * NPIX + n0 + px];
            s += v[i];
            q = fmaf(v[i], v[i], q);
        }
        sp[cg * 32 + px] = s;
        sq[cg * 32 + px] = q;
        __syncthreads();
        float ts = 0.0f, tq = 0.0f;
#pragma unroll
        for (int j = 0; j < 16; ++j) {
            ts += sp[j * 32 + px];
            tq += sq[j * 32 + px];
        }
        float mean = ts * (1.0f / DIMC);
        float rstd = rsqrtf(tq * (1.0f / DIMC) - mean * mean + 1e-5f);
#pragma unroll
        for (int i = 0; i < 16; ++i) {
            int cc = cg * 16 + i;
            y1[(size_t)cc * NPIX + n0 + px] =
                (v[i] - mean) * rstd * s1g[cc] + s1b[cc] + pos[cc] + Es[cc * 33 + px];
        }
        __syncthreads();
        s = 0.0f; q = 0.0f;
#pragma unroll
        for (int i = 0; i < 16; ++i) {
            v[i] = s2x[(size_t)(cg * 16 + i) * NPIX + n0 + px];
            s += v[i];
            q = fmaf(v[i], v[i], q);
        }
        sp[cg * 32 + px] = s;
        sq[cg * 32 + px] = q;
        __syncthreads();
        ts = 0.0f; tq = 0.0f;
#pragma unroll
        for (int j = 0; j < 16; ++j) {
            ts += sp[j * 32 + px];
            tq += sq[j * 32 + px];
        }
        mean = ts * (1.0f / DIMC);
        rstd = rsqrtf(tq * (1.0f / DIMC) - mean * mean + 1e-5f);
#pragma unroll
        for (int i = 0; i < 16; ++i) {
            int cc = cg * 16 + i;
            y2[(size_t)cc * NPIX + n0 + px] =
                (v[i] - mean) * rstd * s2g[cc] + s2b[cc] + pos[cc] + Es[cc * 33 + px];
        }
    }
}

// ---------------------------------------------------------------------------
// Flash attention, fp16 HMMA + MUFU exp2 + ldmatrix, with P KEPT IN REGISTERS:
// QK accumulator layout == PV A-fragment layout (rows r0/r1 = g/g+8, cols
// ns*8+2tg), so pa[ks] = packh2 of sc[2ks]/sc[2ks+1] directly. Removes the
// 16 STS + 4 LDSM + 2 syncwarp per warp-tile P round-trip. Math bit-identical.
// ---------------------------------------------------------------------------
#define FL_SMEM 37888

__global__ void __launch_bounds__(256, 2)
flash_mma(const __half* __restrict__ Q16, const __half* __restrict__ K16,
          const __half* __restrict__ V16, float* __restrict__ O) {
    extern __shared__ uint32_t fsm[];
    uint32_t* Ks = fsm;               // [2][64][20]
    uint32_t* Vs = fsm + 2560;        // [2][32][36]
    uint32_t* Ps = fsm + 4864;        // Q staging only ([128][20] region)

    int tid = threadIdx.x;
    int wid = tid >> 5, lane = tid & 31;
    int g = lane >> 2, tg = lane & 3;
    int h = blockIdx.y;
    int n0 = blockIdx.x * 128;
    int r0 = wid * 16 + g, r1 = r0 + 8;

    const __half* Qh = Q16 + (size_t)h * 32 * NPIX;
    const __half* Kh = K16 + (size_t)h * 32 * NPIX;
    const uint32_t* Vhu = (const uint32_t*)(V16 + (size_t)h * 32 * NPIX);

    uint32_t ks_b = s2u(fsm);
    uint32_t vs_b = ks_b + 2560 * 4;
    uint32_t kfrag = (uint32_t)((lane & 7) + ((lane >> 4) & 1) * 8) * 80
                   + (uint32_t)((lane >> 3) & 1) * 16;
    uint32_t vfrag = (uint32_t)((lane & 7) + ((lane >> 4) & 1) * 8) * 144
                   + (uint32_t)((lane >> 3) & 1) * 16;

    int kkey = tid & 63, kds = tid >> 6;
    int vd = tid >> 4, vslot = tid & 15;

    __half kr[2][4];
    uint2 vr[2];
#pragma unroll
    for (int i = 0; i < 2; ++i) {
        int ds = kds + i * 4;
#pragma unroll
        for (int j = 0; j < 4; ++j)
            kr[i][j] = Kh[(size_t)(ds * 4 + j) * NPIX + kkey];
        vr[i] = *(const uint2*)(Vhu + (size_t)(vd + i * 16) * 2048 + vslot * 2);
    }

    __half* Qsh = (__half*)Ps;
#pragma unroll
    for (int it = 0; it < 4; ++it) {
        int t = tid + it * 256;
        int q4 = t & 31, d = t >> 5;
        uint2 qv = *(const uint2*)(Qh + (size_t)d * NPIX + n0 + q4 * 4);
        const __half* qp = (const __half*)&qv;
        Qsh[(q4 * 4 + 0) * 40 + d] = qp[0];
        Qsh[(q4 * 4 + 1) * 40 + d] = qp[1];
        Qsh[(q4 * 4 + 2) * 40 + d] = qp[2];
        Qsh[(q4 * 4 + 3) * 40 + d] = qp[3];
    }
    __syncthreads();
    uint32_t qa[2][4];
#pragma unroll
    for (int ks = 0; ks < 2; ++ks) {
        int kc = ks * 8 + tg;
        qa[ks][0] = Ps[r0 * 20 + kc];
        qa[ks][1] = Ps[r1 * 20 + kc];
        qa[ks][2] = Ps[r0 * 20 + kc + 4];
        qa[ks][3] = Ps[r1 * 20 + kc + 4];
    }
#pragma unroll
    for (int i = 0; i < 2; ++i) {
        int ds = kds + i * 4;
        *(uint2*)(Ks + kkey * 20 + ds * 2) =
            make_uint2(packhh(kr[i][0], kr[i][1]), packhh(kr[i][2], kr[i][3]));
        *(uint2*)(Vs + (vd + i * 16) * 36 + vslot * 2) = vr[i];
    }
    __syncthreads();

    float m0s = -1e30f, m1s = -1e30f, l0 = 0.0f, l1 = 0.0f;
    float oa[4][4];
#pragma unroll
    for (int u = 0; u < 4; ++u)
#pragma unroll
        for (int e = 0; e < 4; ++e) oa[u][e] = 0.0f;

    for (int kt = 0; kt < 64; ++kt) {
        if (kt + 1 < 64) {
            int mg = (kt + 1) * 64;
#pragma unroll
            for (int i = 0; i < 2; ++i) {
                int ds = kds + i * 4;
#pragma unroll
                for (int j = 0; j < 4; ++j)
                    kr[i][j] = Kh[(size_t)(ds * 4 + j) * NPIX + mg + kkey];
                vr[i] = *(const uint2*)(Vhu + (size_t)(vd + i * 16) * 2048 + (mg >> 1) + vslot * 2);
            }
        }

        uint32_t KsA = ks_b + (kt & 1) * 5120;
        uint32_t VsA = vs_b + (kt & 1) * 4608;

        // ---- scores S = Q K^T (ldmatrix B-frags)
        float sc[8][4];
#pragma unroll
        for (int ns = 0; ns < 8; ++ns)
#pragma unroll
            for (int e = 0; e < 4; ++e) sc[ns][e] = 0.0f;
#pragma unroll
        for (int ks = 0; ks < 2; ++ks) {
#pragma unroll
            for (int nb = 0; nb < 4; ++nb) {
                uint32_t bb[4];
                LDSM4(bb, KsA + nb * 1280 + kfrag + ks * 32);
                mma_f16(sc[2 * nb], qa[ks], bb);
                mma_f16(sc[2 * nb + 1], qa[ks], bb + 2);
            }
        }

        // ---- online softmax (base-2), P computed IN PLACE in sc
        float mx0 = -1e30f, mx1 = -1e30f;
#pragma unroll
        for (int ns = 0; ns < 8; ++ns) {
            mx0 = fmaxf(mx0, fmaxf(sc[ns][0], sc[ns][1]));
            mx1 = fmaxf(mx1, fmaxf(sc[ns][2], sc[ns][3]));
        }
        mx0 = fmaxf(mx0, __shfl_xor_sync(0xffffffffu, mx0, 1));
        mx0 = fmaxf(mx0, __shfl_xor_sync(0xffffffffu, mx0, 2));
        mx1 = fmaxf(mx1, __shfl_xor_sync(0xffffffffu, mx1, 1));
        mx1 = fmaxf(mx1, __shfl_xor_sync(0xffffffffu, mx1, 2));
        float mn0 = fmaxf(m0s, mx0), mn1 = fmaxf(m1s, mx1);
        float c0f = fexp2(m0s - mn0), c1f = fexp2(m1s - mn1);
        float rs0 = 0.0f, rs1 = 0.0f;
#pragma unroll
        for (int ns = 0; ns < 8; ++ns) {
            sc[ns][0] = fexp2(sc[ns][0] - mn0);
            sc[ns][1] = fexp2(sc[ns][1] - mn0);
            sc[ns][2] = fexp2(sc[ns][2] - mn1);
            sc[ns][3] = fexp2(sc[ns][3] - mn1);
            rs0 += sc[ns][0] + sc[ns][1];
            rs1 += sc[ns][2] + sc[ns][3];
        }
        rs0 += __shfl_xor_sync(0xffffffffu, rs0, 1);
        rs0 += __shfl_xor_sync(0xffffffffu, rs0, 2);
        rs1 += __shfl_xor_sync(0xffffffffu, rs1, 1);
        rs1 += __shfl_xor_sync(0xffffffffu, rs1, 2);
        l0 = l0 * c0f + rs0;
        l1 = l1 * c1f + rs1;
        m0s = mn0; m1s = mn1;
#pragma unroll
        for (int u = 0; u < 4; ++u) {
            oa[u][0] *= c0f; oa[u][1] *= c0f;
            oa[u][2] *= c1f; oa[u][3] *= c1f;
        }

        // ---- O += P V: P packed directly from sc (A-frag layout identity)
#pragma unroll
        for (int ks = 0; ks < 4; ++ks) {
            uint32_t pa[4], v0[4], v1[4];
            pa[0] = packh2(sc[2 * ks][0], sc[2 * ks][1]);
            pa[1] = packh2(sc[2 * ks][2], sc[2 * ks][3]);
            pa[2] = packh2(sc[2 * ks + 1][0], sc[2 * ks + 1][1]);
            pa[3] = packh2(sc[2 * ks + 1][2], sc[2 * ks + 1][3]);
            LDSM4(v0, VsA + vfrag + ks * 32);
            LDSM4(v1, VsA + vfrag + 2304 + ks * 32);
            mma_f16(oa[0], pa, v0);
            mma_f16(oa[1], pa, v0 + 2);
            mma_f16(oa[2], pa, v1);
            mma_f16(oa[3], pa, v1 + 2);
        }

        if (kt + 1 < 64) {
            uint32_t* Ksn = Ks + ((kt + 1) & 1) * 1280;
            uint32_t* Vsn = Vs + ((kt + 1) & 1) * 1152;
#pragma unroll
            for (int i = 0; i < 2; ++i) {
                int ds = kds + i * 4;
                *(uint2*)(Ksn + kkey * 20 + ds * 2) =
                    make_uint2(packhh(kr[i][0], kr[i][1]), packhh(kr[i][2], kr[i][3]));
                *(uint2*)(Vsn + (vd + i * 16) * 36 + vslot * 2) = vr[i];
            }
            __syncthreads();
        }
    }

    float il0 = 1.0f / l0, il1 = 1.0f / l1;
#pragma unroll
    for (int ns = 0; ns < 4; ++ns) {
        int d0 = ns * 8 + 2 * tg;
        O[(size_t)(h * 32 + d0) * NPIX + n0 + r0] = oa[ns][0] * il0;
        O[(size_t)(h * 32 + d0 + 1) * NPIX + n0 + r0] = oa[ns][1] * il0;
        O[(size_t)(h * 32 + d0) * NPIX + n0 + r1] = oa[ns][2] * il1;
        O[(size_t)(h * 32 + d0 + 1) * NPIX + n0 + r1] = oa[ns][3] * il1;
    }
}

// ---------------------------------------------------------------------------
extern "C" void kernel_launch(void* const* d_in, const int* in_sizes, int n_in,
                              void* d_out, int out_size) {
    const float* rgb   = (const float*)d_in[0];
    const float* dpt   = (const float*)d_in[1];
    const float* xdpt  = (const float*)d_in[2];
    const float* wq    = (const float*)d_in[3];
    const float* bq    = (const float*)d_in[4];
    const float* wk    = (const float*)d_in[5];
    const float* bk    = (const float*)d_in[6];
    const float* wv    = (const float*)d_in[7];
    const float* bv    = (const float*)d_in[8];
    const float* wo    = (const float*)d_in[9];
    const float* bo    = (const float*)d_in[10];
    const float* ga_rgb = (const float*)d_in[11];
    const float* be_rgb = (const float*)d_in[12];
    const float* ga_dpt = (const float*)d_in[13];
    const float* be_dpt = (const float*)d_in[14];
    const float* ga1   = (const float*)d_in[15];
    const float* be1   = (const float*)d_in[16];
    const float* ga2   = (const float*)d_in[17];
    const float* be2   = (const float*)d_in[18];
    const float* w_mlp1 = (const float*)d_in[19];
    const float* b_mlp1 = (const float*)d_in[20];
    const float* w_mlp2 = (const float*)d_in[21];
    const float* b_mlp2 = (const float*)d_in[22];
    const float* w_de1 = (const float*)d_in[23];
    const float* b_de1 = (const float*)d_in[24];
    const float* w_de2 = (const float*)d_in[25];
    const float* b_de2 = (const float*)d_in[26];
    const float* pos_emb = (const float*)d_in[27];
    const float* scale = (const float*)d_in[28];
    float* out = (float*)d_out;

    float *p_xd, *p_r1, *p_rgbln, *p_dptln, *p_fused, *p_oln, *p_h;
    __half *p_q16, *p_k16, *p_v16, *p_w16;
    cudaGetSymbolAddress((void**)&p_xd, g_xd);
    cudaGetSymbolAddress((void**)&p_r1, g_r1);
    cudaGetSymbolAddress((void**)&p_rgbln, g_rgbln);
    cudaGetSymbolAddress((void**)&p_dptln, g_dptln);
    cudaGetSymbolAddress((void**)&p_q16, g_q16);
    cudaGetSymbolAddress((void**)&p_k16, g_k16);
    cudaGetSymbolAddress((void**)&p_v16, g_v16);
    cudaGetSymbolAddress((void**)&p_fused, g_fused);
    cudaGetSymbolAddress((void**)&p_oln, g_oln);
    cudaGetSymbolAddress((void**)&p_h, g_h);
    cudaGetSymbolAddress((void**)&p_w16, g_w16);

    static bool attr_done = false;
    if (!attr_done) {
        cudaFuncSetAttribute(gemm_mma<2, 0>, cudaFuncAttributeMaxDynamicSharedMemorySize, GEMM_SMEM);
        cudaFuncSetAttribute(gemm_qkv, cudaFuncAttributeMaxDynamicSharedMemorySize, GEMM_SMEM);
        cudaFuncSetAttribute(gemm_ln<0>, cudaFuncAttributeMaxDynamicSharedMemorySize, GLN_SMEM);
        cudaFuncSetAttribute(gemm_ln<1>, cudaFuncAttributeMaxDynamicSharedMemorySize, GLN_SMEM);
        cudaFuncSetAttribute(flash_mma, cudaFuncAttributeMaxDynamicSharedMemorySize, FL_SMEM);
        attr_done = true;
    }

    // weights -> fp16 pool
    cvt_weights<<<dim3(128, 7), 256>>>(w_de2, wq, wk, wv, wo, w_mlp1, w_mlp2, p_w16);

    // depth positional-embedding path
    downsample_kernel<<<16, 256>>>(xdpt, p_xd);
    conv3_kernel<<<256, 256>>>(p_xd, w_de1, b_de1, p_r1);

    // pe GEMM fused with LN(rgb)+pos+pe and LN(dpt)+pos+pe
    gemm_ln<0><<<128, 512, GLN_SMEM>>>(p_w16 + OFF_DE2, p_r1, b_de2, nullptr, nullptr, nullptr,
                                       nullptr, DIMC,
                                       rgb, ga_rgb, be_rgb, dpt, ga_dpt, be_dpt,
                                       pos_emb, p_rgbln, p_dptln);

    // QKV projections
    gemm_qkv<<<dim3(64, 2, 3), 256, GEMM_SMEM>>>(p_w16, bq, bk, bv,
                                                 p_rgbln, p_dptln, p_q16, p_k16, p_v16, scale);

    // flash attention (P-in-registers)
    flash_mma<<<dim3(32, 8), 256, FL_SMEM>>>(p_q16, p_k16, p_v16, p_fused);

    // output proj + residual + LN1 fused -> oln
    gemm_ln<1><<<128, 512, GLN_SMEM>>>(p_w16 + OFF_O, p_fused, bo, rgb, ga1, be1,
                                       p_oln, DIMC,
                                       nullptr, nullptr, nullptr, nullptr, nullptr,
                                       nullptr, nullptr, nullptr, nullptr);

    // MLP up (exact gelu), fp32 output
    gemm_mma<2, 0><<<dim3(64, 8), 256, GEMM_SMEM>>>(p_w16 + OFF_M1, p_oln, b_mlp1, (void*)p_h,
                                                    MLPC, DIMC, NPIX);

    // MLP down + residual + final LN fused -> d_out
    gemm_ln<1><<<128, 512, GLN_SMEM>>>(p_w16 + OFF_M2, p_h, b_mlp2, p_oln, ga2, be2,
                                       out, MLPC,
                                       nullptr, nullptr, nullptr, nullptr, nullptr,
                                       nullptr, nullptr, nullptr, nullptr);
}